// round 11
// baseline (speedup 1.0000x reference)
#include <cuda_runtime.h>
#include <cuda_fp16.h>
#include <math.h>
#include <stdint.h>

#define B_     8
#define C_     512
#define HH     64
#define WW     64
#define NPIX   4096
#define HEADS_ 8
#define HD     64
#define TOFF   (B_ * C_ * NPIX)
#define NSPLIT 16

// ---------------- scratch ----------------
__device__ __align__(16) __half g_y [TOFF];
__device__ __align__(16) __half g_q [TOFF], g_k[TOFF], g_v[TOFF];
__device__ __align__(16) __half g_ao[TOFF];
__device__ __align__(16) __half g_wh[4 * C_ * C_];
__device__ __align__(16) __half g_at[B_ * HEADS_ * HD * HD];
__device__ float g_part[B_ * HEADS_ * NSPLIT * HD * HD];
__device__ float g_sq[3 * B_ * C_];

// ---------------- PTX helpers (baseline sm_80+) ----------------
__device__ __forceinline__ uint32_t smem_u32(const void* p) {
    uint32_t a;
    asm("{ .reg .u64 t; cvta.to.shared.u64 t, %1; cvt.u32.u64 %0, t; }" : "=r"(a) : "l"(p));
    return a;
}
#define CP16(s, g) asm volatile("cp.async.cg.shared.global [%0], [%1], 16;" :: "r"(s), "l"(g))
#define CP_COMMIT() asm volatile("cp.async.commit_group;" ::: "memory")
#define CP_WAIT(n)  asm volatile("cp.async.wait_group %0;" :: "n"(n) : "memory")
#define CP_WAIT0()  asm volatile("cp.async.wait_group 0;" ::: "memory")

#define LDSM_X4(r, a) \
    asm volatile("ldmatrix.sync.aligned.m8n8.x4.shared.b16 {%0,%1,%2,%3}, [%4];" \
        : "=r"((r)[0]), "=r"((r)[1]), "=r"((r)[2]), "=r"((r)[3]) : "r"(a))
#define LDSM_X4T(r, a) \
    asm volatile("ldmatrix.sync.aligned.m8n8.x4.trans.shared.b16 {%0,%1,%2,%3}, [%4];" \
        : "=r"((r)[0]), "=r"((r)[1]), "=r"((r)[2]), "=r"((r)[3]) : "r"(a))
#define MMA16816(d, a, b0, b1) \
    asm volatile("mma.sync.aligned.m16n8k16.row.col.f32.f16.f16.f32 " \
        "{%0,%1,%2,%3}, {%4,%5,%6,%7}, {%8,%9}, {%0,%1,%2,%3};" \
        : "+f"((d)[0]), "+f"((d)[1]), "+f"((d)[2]), "+f"((d)[3]) \
        : "r"((a)[0]), "r"((a)[1]), "r"((a)[2]), "r"((a)[3]), "r"(b0), "r"(b1))

__device__ __forceinline__ uint32_t sw128(uint32_t o) { return o ^ ((o >> 3) & 0x70); }

__device__ __forceinline__ uint32_t pack2h(__half a, __half b) {
    unsigned short ua = *(unsigned short*)&a, ub = *(unsigned short*)&b;
    return (uint32_t)ua | ((uint32_t)ub << 16);
}
__device__ __forceinline__ float inv_norm(float s) {
    return 1.0f / fmaxf(sqrtf(s), 1e-12f);
}

// ---------------- depthwise 3x3 -> fp16 ----------------
__global__ __launch_bounds__(256) void dwconv_kernel(const float* __restrict__ x,
                                                     const float* __restrict__ w) {
    int plane = blockIdx.y;
    int c = plane & (C_ - 1);
    __shared__ float ws[9];
    if (threadIdx.x < 9) ws[threadIdx.x] = w[c * 9 + threadIdx.x];
    __syncthreads();
    int p = blockIdx.x * 256 + threadIdx.x;
    int h = p >> 6, wc = p & 63;
    const float* xp = x + (size_t)plane * NPIX;
    float acc = 0.f;
#pragma unroll
    for (int kh = 0; kh < 3; kh++) {
        int hh = h + kh - 1;
        if (hh < 0 || hh >= HH) continue;
#pragma unroll
        for (int kw = 0; kw < 3; kw++) {
            int wcol = wc + kw - 1;
            if (wcol < 0 || wcol >= WW) continue;
            acc = fmaf(ws[kh * 3 + kw], xp[hh * WW + wcol], acc);
        }
    }
    g_y[(size_t)plane * NPIX + p] = __float2half_rn(acc);
}

// ---------------- weight conversion (+ zero g_sq) ----------------
__global__ __launch_bounds__(256) void convert_w_kernel(const float* __restrict__ qw,
                                                        const float* __restrict__ kw,
                                                        const float* __restrict__ vw,
                                                        const float* __restrict__ pw) {
    int idx = blockIdx.x * 256 + threadIdx.x;
    if (blockIdx.x < 48) {
        int zi = blockIdx.x * 256 + threadIdx.x;
        if (zi < 3 * B_ * C_) g_sq[zi] = 0.f;
    }
    int m = idx >> 18;
    const float* src = (m == 0) ? qw : (m == 1) ? kw : (m == 2) ? vw : pw;
    g_wh[idx] = __float2half_rn(src[idx & 262143]);
}

// ---------------- 1-term fp16 GEMM, CTA 128x128, 512 threads, 3-stage ----------------
// OUTMODE 0: write q/k/v fp16 + per-row sumsq. OUTMODE 1: write fp32 Cout.
#define Q_A 0
#define Q_B 16384
#define Q_STAGE 32768
#define Q_SMEM (3 * Q_STAGE)

template <int OUTMODE>
__global__ __launch_bounds__(512, 2) void gemm1_kernel(const __half* __restrict__ Wh,
                                                       const __half* __restrict__ Bg,
                                                       float* __restrict__ Cout) {
    extern __shared__ char smem[];
    uint32_t sb = smem_u32(smem);
    int tid = threadIdx.x;
    int l = tid & 31, wid = tid >> 5;     // 16 warps
    int wm = wid & 3, wn = wid >> 2;      // warp tile: 32 rows x 32 cols
    int bn = blockIdx.x * 128;
    int bm = blockIdx.y * 128;
    int bz = blockIdx.z;
    const __half* Bp = Bg + (size_t)bz * C_ * NPIX;

    auto load_chunk = [&](int chunk, int stg) {
        uint32_t st = sb + stg * Q_STAGE;
        int k0 = chunk * 64;
#pragma unroll
        for (int it = 0; it < 2; it++) {
            int idx = tid + it * 512;              // 0..1023
            int ar = idx >> 3;                     // 0..127
            int ac = (idx & 7) << 3;
            uint32_t aswo = sw128((uint32_t)(ar * 128 + ac * 2));
            CP16(st + Q_A + aswo, Wh + (size_t)(bm + ar) * C_ + k0 + ac);
            int brr = idx >> 4;                    // 0..63
            int bnn = (idx & 15) << 3;             // 0..120
            int s = bnn >> 6, nl = bnn & 63;
            uint32_t bswo = (uint32_t)(s * 8192) + sw128((uint32_t)(brr * 128 + nl * 2));
            CP16(st + Q_B + bswo, Bp + (size_t)(k0 + brr) * NPIX + bn + bnn);
        }
    };

    float acc[2][4][4] = {};
    int lr = l & 15;
    int lc = (l >> 4) << 4;

    load_chunk(0, 0); CP_COMMIT();
    load_chunk(1, 1); CP_COMMIT();

    for (int chunk = 0; chunk < 8; chunk++) {
        CP_WAIT(1);
        __syncthreads();
        uint32_t st = sb + (chunk % 3) * Q_STAGE;
#pragma unroll
        for (int k16 = 0; k16 < 4; k16++) {
            uint32_t ah[2][4], bf[2][4];
#pragma unroll
            for (int mt = 0; mt < 2; mt++) {
                uint32_t swo = sw128((uint32_t)((wm * 32 + mt * 16 + lr) * 128 + k16 * 32 + lc));
                LDSM_X4(ah[mt], st + Q_A + swo);
            }
            uint32_t pb = (uint32_t)((wn >> 1) * 8192);
#pragma unroll
            for (int h = 0; h < 2; h++) {
                uint32_t swo = sw128((uint32_t)((k16 * 16 + lr) * 128 + (wn & 1) * 64 + h * 32 + lc));
                LDSM_X4T(bf[h], st + Q_B + pb + swo);
            }
#pragma unroll
            for (int mt = 0; mt < 2; mt++)
#pragma unroll
                for (int nt = 0; nt < 4; nt++) {
                    int h = nt >> 1, pr = (nt & 1) * 2;
                    MMA16816(acc[mt][nt], ah[mt], bf[h][pr], bf[h][pr + 1]);
                }
        }
        __syncthreads();
        if (chunk + 2 < 8) load_chunk(chunk + 2, (chunk + 2) % 3);
        CP_COMMIT();
    }

    int l4 = l >> 2, l2 = (l & 3) << 1;
    if (OUTMODE == 0) {
#pragma unroll
        for (int mt = 0; mt < 2; mt++) {
#pragma unroll
            for (int half = 0; half < 2; half++) {
                int row = bm + wm * 32 + mt * 16 + l4 + half * 8;
                int which = row >> 9, ml = row & 511;
                __half* pq = ((which == 0) ? g_q : (which == 1) ? g_k : g_v)
                             + ((size_t)bz * C_ + ml) * NPIX;
                float ss = 0.f;
#pragma unroll
                for (int nt = 0; nt < 4; nt++) {
                    int col = bn + wn * 32 + nt * 8 + l2;
                    float v0 = acc[mt][nt][half * 2], v1 = acc[mt][nt][half * 2 + 1];
                    ss += v0 * v0 + v1 * v1;
                    *(uint32_t*)(pq + col) = pack2h(__float2half_rn(v0), __float2half_rn(v1));
                }
                ss += __shfl_xor_sync(0xffffffffu, ss, 1);
                ss += __shfl_xor_sync(0xffffffffu, ss, 2);
                if ((l & 3) == 0)
                    atomicAdd(&g_sq[which * (B_ * C_) + bz * C_ + ml], ss);
            }
        }
    } else {
#pragma unroll
        for (int mt = 0; mt < 2; mt++) {
#pragma unroll
            for (int half = 0; half < 2; half++) {
                int row = bm + wm * 32 + mt * 16 + l4 + half * 8;
                float* base = Cout + ((size_t)bz * C_ + row) * NPIX;
#pragma unroll
                for (int nt = 0; nt < 4; nt++) {
                    int col = bn + wn * 32 + nt * 8 + l2;
                    *(float2*)(base + col) =
                        make_float2(acc[mt][nt][half * 2], acc[mt][nt][half * 2 + 1]);
                }
            }
        }
    }
}

// ---------------- scores: fp16 HMMA, 16-way split-K partials ----------------
#define SC_Q 0
#define SC_K 8192
#define SC_STAGE 16384
#define SC_SMEM (2 * SC_STAGE)

__global__ __launch_bounds__(256) void scores_kernel() {
    extern __shared__ char smem[];
    uint32_t sb = smem_u32(smem);
    int sp = blockIdx.x, bh = blockIdx.y;
    int b = bh >> 3, hg = bh & 7;
    int tid = threadIdx.x, l = tid & 31, wid = tid >> 5;
    int wm = wid & 1, wn = wid >> 1;
    const __half* qp = g_q + ((size_t)b * C_ + hg * HD) * NPIX;
    const __half* kp = g_k + ((size_t)b * C_ + hg * HD) * NPIX;
    int px0 = sp * 256;

    auto load_chunk = [&](int chunk, int stg) {
        uint32_t st = sb + stg * SC_STAGE;
        int k0 = px0 + chunk * 64;
#pragma unroll
        for (int it = 0; it < 2; it++) {
            int idx = tid + it * 256;
            int r = idx >> 3;
            int c8 = idx & 7;
            uint32_t swo = sw128((uint32_t)(r * 128 + c8 * 16));
            size_t go = (size_t)r * NPIX + k0 + c8 * 8;
            CP16(st + SC_Q + swo, qp + go);
            CP16(st + SC_K + swo, kp + go);
        }
    };

    float acc[2][2][4] = {};
    int lr = l & 15, lc = (l >> 4) << 4;
    int bn_row = wn * 16 + (l & 7) + ((l >> 4) << 3);
    int bn_kb = ((l >> 3) & 1) * 16;

    load_chunk(0, 0); CP_COMMIT();
    load_chunk(1, 1); CP_COMMIT();

    for (int chunk = 0; chunk < 4; chunk++) {
        CP_WAIT(1);
        __syncthreads();
        uint32_t st = sb + (chunk & 1) * SC_STAGE;
#pragma unroll
        for (int k16 = 0; k16 < 4; k16++) {
            uint32_t ah[2][4], bf[4];
#pragma unroll
            for (int mt = 0; mt < 2; mt++) {
                uint32_t swo = sw128((uint32_t)((wm * 32 + mt * 16 + lr) * 128 + k16 * 32 + lc));
                LDSM_X4(ah[mt], st + SC_Q + swo);
            }
            uint32_t swb = sw128((uint32_t)(bn_row * 128 + k16 * 32 + bn_kb));
            LDSM_X4(bf, st + SC_K + swb);
#pragma unroll
            for (int mt = 0; mt < 2; mt++)
#pragma unroll
                for (int nt = 0; nt < 2; nt++)
                    MMA16816(acc[mt][nt], ah[mt], bf[nt * 2], bf[nt * 2 + 1]);
        }
        __syncthreads();
        if (chunk + 2 < 4) load_chunk(chunk + 2, chunk & 1);
        CP_COMMIT();
    }

    float* op = g_part + ((size_t)bh * NSPLIT + sp) * 4096;
    int l4 = l >> 2, l2 = (l & 3) << 1;
#pragma unroll
    for (int mt = 0; mt < 2; mt++)
#pragma unroll
        for (int half = 0; half < 2; half++) {
            int row = wm * 32 + mt * 16 + l4 + half * 8;
#pragma unroll
            for (int nt = 0; nt < 2; nt++) {
                int col = wn * 16 + nt * 8 + l2;
                *(float2*)(op + row * 64 + col) =
                    make_float2(acc[mt][nt][half * 2], acc[mt][nt][half * 2 + 1]);
            }
        }
}

// ---------------- reduce + softmax, fold norms, -> attn fp16 ----------------
__global__ __launch_bounds__(256) void softmax_kernel() {
    int bh = blockIdx.x;
    int b = bh >> 3, hg = bh & 7;
    int cb = b * C_ + hg * HD;
    __shared__ float Ss[64][64];
    __shared__ float rv_s[64];
    int tid = threadIdx.x;
    const float scale = 0.125f;
    if (tid < 64) rv_s[tid] = inv_norm(g_sq[2 * B_ * C_ + cb + tid]);
    for (int i = tid; i < 4096; i += 256) {
        float s = 0.f;
#pragma unroll
        for (int p = 0; p < NSPLIT; p++) s += g_part[((size_t)bh * NSPLIT + p) * 4096 + i];
        int r = i >> 6, c = i & 63;
        Ss[r][c] = s * inv_norm(g_sq[cb + r]) * scale * inv_norm(g_sq[B_ * C_ + cb + c]);
    }
    __syncthreads();
    int warp = tid >> 5, lane = tid & 31;
#pragma unroll
    for (int rr = 0; rr < 8; rr++) {
        int r = warp * 8 + rr;
        float v0 = Ss[r][lane], v1 = Ss[r][lane + 32];
        float m = fmaxf(v0, v1);
#pragma unroll
        for (int off = 16; off; off >>= 1) m = fmaxf(m, __shfl_xor_sync(0xffffffffu, m, off));
        float e0 = __expf(v0 - m), e1 = __expf(v1 - m);
        float s = e0 + e1;
#pragma unroll
        for (int off = 16; off; off >>= 1) s += __shfl_xor_sync(0xffffffffu, s, off);
        float inv = 1.0f / s;
        size_t base = (size_t)bh * 4096 + r * 64;
        g_at[base + lane]      = __float2half_rn(e0 * inv * rv_s[lane]);
        g_at[base + lane + 32] = __float2half_rn(e1 * inv * rv_s[lane + 32]);
    }
}

// ---------------- apply: fp16 HMMA out = attn @ v -> ao fp16 ----------------
#define AP_A 0
#define AP_V 8192
#define AP_SMEM 24576

__global__ __launch_bounds__(256) void apply_kernel() {
    extern __shared__ char smem[];
    uint32_t sb = smem_u32(smem);
    int ntile = blockIdx.x;
    int bh = blockIdx.y;
    int b = bh >> 3, hg = bh & 7;
    int tid = threadIdx.x, l = tid & 31, wid = tid >> 5;
    int wm = wid & 1, wn = wid >> 1;

#pragma unroll
    for (int it = 0; it < 2; it++) {
        int idx = tid + it * 256;
        int r = idx >> 3, c8 = idx & 7;
        uint32_t swo = sw128((uint32_t)(r * 128 + c8 * 16));
        CP16(sb + AP_A + swo, g_at + (size_t)bh * 4096 + r * 64 + c8 * 8);
    }
    const __half* vp = g_v + ((size_t)b * C_ + hg * HD) * NPIX + ntile * 128;
#pragma unroll
    for (int it = 0; it < 4; it++) {
        int idx = tid + it * 256;
        int r = idx >> 4;
        int n8 = idx & 15;
        int s = n8 >> 3, nl = n8 & 7;
        uint32_t swo = (uint32_t)(s * 8192) + sw128((uint32_t)(r * 128 + nl * 16));
        CP16(sb + AP_V + swo, vp + (size_t)r * NPIX + n8 * 8);
    }
    CP_COMMIT();
    CP_WAIT0();
    __syncthreads();

    float acc[2][4][4] = {};
    int lr = l & 15, lc = (l >> 4) << 4;
#pragma unroll
    for (int k16 = 0; k16 < 4; k16++) {
        uint32_t ah[2][4], bf[2][4];
#pragma unroll
        for (int mt = 0; mt < 2; mt++) {
            uint32_t swo = sw128((uint32_t)((wm * 32 + mt * 16 + lr) * 128 + k16 * 32 + lc));
            LDSM_X4(ah[mt], sb + AP_A + swo);
        }
        uint32_t pb = (uint32_t)((wn >> 1) * 8192);
#pragma unroll
        for (int h = 0; h < 2; h++) {
            uint32_t swo = sw128((uint32_t)((k16 * 16 + lr) * 128 + (wn & 1) * 64 + h * 32 + lc));
            LDSM_X4T(bf[h], sb + AP_V + pb + swo);
        }
#pragma unroll
        for (int mt = 0; mt < 2; mt++)
#pragma unroll
            for (int nt = 0; nt < 4; nt++) {
                int h = nt >> 1, pr = (nt & 1) * 2;
                MMA16816(acc[mt][nt], ah[mt], bf[h][pr], bf[h][pr + 1]);
            }
    }

    int l4 = l >> 2, l2 = (l & 3) << 1;
#pragma unroll
    for (int mt = 0; mt < 2; mt++)
#pragma unroll
        for (int half = 0; half < 2; half++) {
            int row = wm * 32 + mt * 16 + l4 + half * 8;
            __half* po = g_ao + ((size_t)b * C_ + hg * HD + row) * NPIX + ntile * 128;
#pragma unroll
            for (int nt = 0; nt < 4; nt++) {
                int col = wn * 32 + nt * 8 + l2;
                *(uint32_t*)(po + col) =
                    pack2h(__float2half_rn(acc[mt][nt][half * 2]),
                           __float2half_rn(acc[mt][nt][half * 2 + 1]));
            }
        }
}

// ---------------- launch ----------------
extern "C" void kernel_launch(void* const* d_in, const int* in_sizes, int n_in,
                              void* d_out, int out_size) {
    const float* x  = (const float*)d_in[0];
    const float* dw = (const float*)d_in[1];
    const float* qw = (const float*)d_in[2];
    const float* kw = (const float*)d_in[3];
    const float* vw = (const float*)d_in[4];
    const float* pw = (const float*)d_in[5];
    float* out = (float*)d_out;

    __half *yp, *aop, *whp;
    cudaGetSymbolAddress((void**)&yp,  g_y);
    cudaGetSymbolAddress((void**)&aop, g_ao);
    cudaGetSymbolAddress((void**)&whp, g_wh);

    cudaFuncSetAttribute(gemm1_kernel<0>, cudaFuncAttributeMaxDynamicSharedMemorySize, Q_SMEM);
    cudaFuncSetAttribute(gemm1_kernel<1>, cudaFuncAttributeMaxDynamicSharedMemorySize, Q_SMEM);
    cudaFuncSetAttribute(scores_kernel, cudaFuncAttributeMaxDynamicSharedMemorySize, SC_SMEM);
    cudaFuncSetAttribute(apply_kernel,  cudaFuncAttributeMaxDynamicSharedMemorySize, AP_SMEM);

    dwconv_kernel<<<dim3(NPIX / 256, B_ * C_), 256>>>(x, dw);              // 1
    convert_w_kernel<<<4096, 256>>>(qw, kw, vw, pw);                       // 2 (+ zero g_sq)
    // fused QKV GEMM, M=1536, CTA 128x128, 512 threads (profiled slot ~#4)
    gemm1_kernel<0><<<dim3(NPIX / 128, 12, B_), 512, Q_SMEM>>>(whp, yp, nullptr); // 3
    scores_kernel<<<dim3(NSPLIT, B_ * HEADS_), 256, SC_SMEM>>>();          // 4
    softmax_kernel<<<B_ * HEADS_, 256>>>();                                // 5
    apply_kernel<<<dim3(NPIX / 128, B_ * HEADS_), 256, AP_SMEM>>>();       // 6
    // proj GEMM: 1-term, CTA 128x128, 512 threads, weight rows [1536, 2048)
    gemm1_kernel<1><<<dim3(NPIX / 128, 4, B_), 512, Q_SMEM>>>(             // 7
        whp + 1536 * C_, aop, out);
}

// round 12
// speedup vs baseline: 1.4686x; 1.4686x over previous
#include <cuda_runtime.h>
#include <cuda_fp16.h>
#include <math.h>
#include <stdint.h>

#define B_     8
#define C_     512
#define HH     64
#define WW     64
#define NPIX   4096
#define HEADS_ 8
#define HD     64
#define TOFF   (B_ * C_ * NPIX)
#define NSPLIT 16

// ---------------- scratch ----------------
__device__ __align__(16) __half g_y [TOFF];
__device__ __align__(16) __half g_q [TOFF], g_k[TOFF], g_v[TOFF];
__device__ __align__(16) __half g_ao[TOFF];
__device__ __align__(16) __half g_wh[4 * C_ * C_];
__device__ __align__(16) __half g_at[B_ * HEADS_ * HD * HD];
__device__ float g_part[B_ * HEADS_ * NSPLIT * HD * HD];
__device__ float g_sq[3 * B_ * C_];

// ---------------- PTX helpers (baseline sm_80+) ----------------
__device__ __forceinline__ uint32_t smem_u32(const void* p) {
    uint32_t a;
    asm("{ .reg .u64 t; cvta.to.shared.u64 t, %1; cvt.u32.u64 %0, t; }" : "=r"(a) : "l"(p));
    return a;
}
#define CP16(s, g) asm volatile("cp.async.cg.shared.global [%0], [%1], 16;" :: "r"(s), "l"(g))
#define CP_COMMIT() asm volatile("cp.async.commit_group;" ::: "memory")
#define CP_WAIT(n)  asm volatile("cp.async.wait_group %0;" :: "n"(n) : "memory")
#define CP_WAIT0()  asm volatile("cp.async.wait_group 0;" ::: "memory")

#define LDSM_X4(r, a) \
    asm volatile("ldmatrix.sync.aligned.m8n8.x4.shared.b16 {%0,%1,%2,%3}, [%4];" \
        : "=r"((r)[0]), "=r"((r)[1]), "=r"((r)[2]), "=r"((r)[3]) : "r"(a))
#define LDSM_X4T(r, a) \
    asm volatile("ldmatrix.sync.aligned.m8n8.x4.trans.shared.b16 {%0,%1,%2,%3}, [%4];" \
        : "=r"((r)[0]), "=r"((r)[1]), "=r"((r)[2]), "=r"((r)[3]) : "r"(a))
#define MMA16816(d, a, b0, b1) \
    asm volatile("mma.sync.aligned.m16n8k16.row.col.f32.f16.f16.f32 " \
        "{%0,%1,%2,%3}, {%4,%5,%6,%7}, {%8,%9}, {%0,%1,%2,%3};" \
        : "+f"((d)[0]), "+f"((d)[1]), "+f"((d)[2]), "+f"((d)[3]) \
        : "r"((a)[0]), "r"((a)[1]), "r"((a)[2]), "r"((a)[3]), "r"(b0), "r"(b1))

__device__ __forceinline__ uint32_t sw128(uint32_t o) { return o ^ ((o >> 3) & 0x70); }

__device__ __forceinline__ uint32_t pack2h(__half a, __half b) {
    unsigned short ua = *(unsigned short*)&a, ub = *(unsigned short*)&b;
    return (uint32_t)ua | ((uint32_t)ub << 16);
}
__device__ __forceinline__ float inv_norm(float s) {
    return 1.0f / fmaxf(sqrtf(s), 1e-12f);
}

// ---------------- depthwise 3x3 -> fp16 ----------------
__global__ __launch_bounds__(256) void dwconv_kernel(const float* __restrict__ x,
                                                     const float* __restrict__ w) {
    int plane = blockIdx.y;
    int c = plane & (C_ - 1);
    __shared__ float ws[9];
    if (threadIdx.x < 9) ws[threadIdx.x] = w[c * 9 + threadIdx.x];
    __syncthreads();
    int p = blockIdx.x * 256 + threadIdx.x;
    int h = p >> 6, wc = p & 63;
    const float* xp = x + (size_t)plane * NPIX;
    float acc = 0.f;
#pragma unroll
    for (int kh = 0; kh < 3; kh++) {
        int hh = h + kh - 1;
        if (hh < 0 || hh >= HH) continue;
#pragma unroll
        for (int kw = 0; kw < 3; kw++) {
            int wcol = wc + kw - 1;
            if (wcol < 0 || wcol >= WW) continue;
            acc = fmaf(ws[kh * 3 + kw], xp[hh * WW + wcol], acc);
        }
    }
    g_y[(size_t)plane * NPIX + p] = __float2half_rn(acc);
}

// ---------------- weight conversion (+ zero g_sq) ----------------
__global__ __launch_bounds__(256) void convert_w_kernel(const float* __restrict__ qw,
                                                        const float* __restrict__ kw,
                                                        const float* __restrict__ vw,
                                                        const float* __restrict__ pw) {
    int idx = blockIdx.x * 256 + threadIdx.x;
    if (blockIdx.x < 48) {
        int zi = blockIdx.x * 256 + threadIdx.x;
        if (zi < 3 * B_ * C_) g_sq[zi] = 0.f;
    }
    int m = idx >> 18;
    const float* src = (m == 0) ? qw : (m == 1) ? kw : (m == 2) ? vw : pw;
    g_wh[idx] = __float2half_rn(src[idx & 262143]);
}

// ---------------- 1-term fp16 GEMM, CTA 128x128, 256 threads, 3-stage ----------------
// OUTMODE 0: write q/k/v fp16 + per-row sumsq. OUTMODE 1: write fp32 Cout.
#define Q_A 0
#define Q_B 16384
#define Q_STAGE 32768
#define Q_SMEM (3 * Q_STAGE)

template <int OUTMODE>
__global__ __launch_bounds__(256, 2) void gemm1_kernel(const __half* __restrict__ Wh,
                                                       const __half* __restrict__ Bg,
                                                       float* __restrict__ Cout) {
    extern __shared__ char smem[];
    uint32_t sb = smem_u32(smem);
    int tid = threadIdx.x;
    int l = tid & 31, wid = tid >> 5;
    int wm = wid & 3, wn = wid >> 2;        // warp tile: 32 rows x 64 cols
    int bn = blockIdx.x * 128;
    int bm = blockIdx.y * 128;
    int bz = blockIdx.z;
    const __half* Bp = Bg + (size_t)bz * C_ * NPIX;

    auto load_chunk = [&](int chunk, int stg) {
        uint32_t st = sb + stg * Q_STAGE;
        int k0 = chunk * 64;
#pragma unroll
        for (int it = 0; it < 4; it++) {
            int idx = tid + it * 256;              // 0..1023
            int ar = idx >> 3;                     // 0..127
            int ac = (idx & 7) << 3;
            uint32_t aswo = sw128((uint32_t)(ar * 128 + ac * 2));
            CP16(st + Q_A + aswo, Wh + (size_t)(bm + ar) * C_ + k0 + ac);
            int brr = idx >> 4;                    // 0..63
            int bnn = (idx & 15) << 3;             // 0..120
            int s = bnn >> 6, nl = bnn & 63;
            uint32_t bswo = (uint32_t)(s * 8192) + sw128((uint32_t)(brr * 128 + nl * 2));
            CP16(st + Q_B + bswo, Bp + (size_t)(k0 + brr) * NPIX + bn + bnn);
        }
    };

    float acc[2][8][4] = {};
    int lr = l & 15;
    int lc = (l >> 4) << 4;

    load_chunk(0, 0); CP_COMMIT();
    load_chunk(1, 1); CP_COMMIT();

    for (int chunk = 0; chunk < 8; chunk++) {
        CP_WAIT(1);
        __syncthreads();
        uint32_t st = sb + (chunk % 3) * Q_STAGE;
#pragma unroll
        for (int k16 = 0; k16 < 4; k16++) {
            uint32_t ah[2][4], bf[4][4];
#pragma unroll
            for (int mt = 0; mt < 2; mt++) {
                uint32_t swo = sw128((uint32_t)((wm * 32 + mt * 16 + lr) * 128 + k16 * 32 + lc));
                LDSM_X4(ah[mt], st + Q_A + swo);
            }
            uint32_t pb = (uint32_t)(wn * 8192);
#pragma unroll
            for (int h = 0; h < 4; h++) {
                uint32_t swo = sw128((uint32_t)((k16 * 16 + lr) * 128 + h * 32 + lc));
                LDSM_X4T(bf[h], st + Q_B + pb + swo);
            }
#pragma unroll
            for (int mt = 0; mt < 2; mt++)
#pragma unroll
                for (int nt = 0; nt < 8; nt++) {
                    int h = nt >> 1, pr = (nt & 1) * 2;
                    MMA16816(acc[mt][nt], ah[mt], bf[h][pr], bf[h][pr + 1]);
                }
        }
        __syncthreads();
        if (chunk + 2 < 8) load_chunk(chunk + 2, (chunk + 2) % 3);
        CP_COMMIT();
    }

    int l4 = l >> 2, l2 = (l & 3) << 1;
    if (OUTMODE == 0) {
#pragma unroll
        for (int mt = 0; mt < 2; mt++) {
#pragma unroll
            for (int half = 0; half < 2; half++) {
                int row = bm + wm * 32 + mt * 16 + l4 + half * 8;
                int which = row >> 9, ml = row & 511;
                __half* pq = ((which == 0) ? g_q : (which == 1) ? g_k : g_v)
                             + ((size_t)bz * C_ + ml) * NPIX;
                float ss = 0.f;
#pragma unroll
                for (int nt = 0; nt < 8; nt++) {
                    int col = bn + wn * 64 + nt * 8 + l2;
                    float v0 = acc[mt][nt][half * 2], v1 = acc[mt][nt][half * 2 + 1];
                    ss += v0 * v0 + v1 * v1;
                    *(uint32_t*)(pq + col) = pack2h(__float2half_rn(v0), __float2half_rn(v1));
                }
                ss += __shfl_xor_sync(0xffffffffu, ss, 1);
                ss += __shfl_xor_sync(0xffffffffu, ss, 2);
                if ((l & 3) == 0)
                    atomicAdd(&g_sq[which * (B_ * C_) + bz * C_ + ml], ss);
            }
        }
    } else {
#pragma unroll
        for (int mt = 0; mt < 2; mt++) {
#pragma unroll
            for (int half = 0; half < 2; half++) {
                int row = bm + wm * 32 + mt * 16 + l4 + half * 8;
                float* base = Cout + ((size_t)bz * C_ + row) * NPIX;
#pragma unroll
                for (int nt = 0; nt < 8; nt++) {
                    int col = bn + wn * 64 + nt * 8 + l2;
                    *(float2*)(base + col) =
                        make_float2(acc[mt][nt][half * 2], acc[mt][nt][half * 2 + 1]);
                }
            }
        }
    }
}

// ---------------- scores: fp16 HMMA, 16-way split-K partials ----------------
#define SC_Q 0
#define SC_K 8192
#define SC_STAGE 16384
#define SC_SMEM (2 * SC_STAGE)

__global__ __launch_bounds__(256) void scores_kernel() {
    extern __shared__ char smem[];
    uint32_t sb = smem_u32(smem);
    int sp = blockIdx.x, bh = blockIdx.y;
    int b = bh >> 3, hg = bh & 7;
    int tid = threadIdx.x, l = tid & 31, wid = tid >> 5;
    int wm = wid & 1, wn = wid >> 1;
    const __half* qp = g_q + ((size_t)b * C_ + hg * HD) * NPIX;
    const __half* kp = g_k + ((size_t)b * C_ + hg * HD) * NPIX;
    int px0 = sp * 256;

    auto load_chunk = [&](int chunk, int stg) {
        uint32_t st = sb + stg * SC_STAGE;
        int k0 = px0 + chunk * 64;
#pragma unroll
        for (int it = 0; it < 2; it++) {
            int idx = tid + it * 256;
            int r = idx >> 3;
            int c8 = idx & 7;
            uint32_t swo = sw128((uint32_t)(r * 128 + c8 * 16));
            size_t go = (size_t)r * NPIX + k0 + c8 * 8;
            CP16(st + SC_Q + swo, qp + go);
            CP16(st + SC_K + swo, kp + go);
        }
    };

    float acc[2][2][4] = {};
    int lr = l & 15, lc = (l >> 4) << 4;
    int bn_row = wn * 16 + (l & 7) + ((l >> 4) << 3);
    int bn_kb = ((l >> 3) & 1) * 16;

    load_chunk(0, 0); CP_COMMIT();
    load_chunk(1, 1); CP_COMMIT();

    for (int chunk = 0; chunk < 4; chunk++) {
        CP_WAIT(1);
        __syncthreads();
        uint32_t st = sb + (chunk & 1) * SC_STAGE;
#pragma unroll
        for (int k16 = 0; k16 < 4; k16++) {
            uint32_t ah[2][4], bf[4];
#pragma unroll
            for (int mt = 0; mt < 2; mt++) {
                uint32_t swo = sw128((uint32_t)((wm * 32 + mt * 16 + lr) * 128 + k16 * 32 + lc));
                LDSM_X4(ah[mt], st + SC_Q + swo);
            }
            uint32_t swb = sw128((uint32_t)(bn_row * 128 + k16 * 32 + bn_kb));
            LDSM_X4(bf, st + SC_K + swb);
#pragma unroll
            for (int mt = 0; mt < 2; mt++)
#pragma unroll
                for (int nt = 0; nt < 2; nt++)
                    MMA16816(acc[mt][nt], ah[mt], bf[nt * 2], bf[nt * 2 + 1]);
        }
        __syncthreads();
        if (chunk + 2 < 4) load_chunk(chunk + 2, chunk & 1);
        CP_COMMIT();
    }

    float* op = g_part + ((size_t)bh * NSPLIT + sp) * 4096;
    int l4 = l >> 2, l2 = (l & 3) << 1;
#pragma unroll
    for (int mt = 0; mt < 2; mt++)
#pragma unroll
        for (int half = 0; half < 2; half++) {
            int row = wm * 32 + mt * 16 + l4 + half * 8;
#pragma unroll
            for (int nt = 0; nt < 2; nt++) {
                int col = wn * 16 + nt * 8 + l2;
                *(float2*)(op + row * 64 + col) =
                    make_float2(acc[mt][nt][half * 2], acc[mt][nt][half * 2 + 1]);
            }
        }
}

// ---------------- reduce + softmax, fold norms, -> attn fp16 ----------------
__global__ __launch_bounds__(256) void softmax_kernel() {
    int bh = blockIdx.x;
    int b = bh >> 3, hg = bh & 7;
    int cb = b * C_ + hg * HD;
    __shared__ float Ss[64][64];
    __shared__ float rv_s[64];
    int tid = threadIdx.x;
    const float scale = 0.125f;
    if (tid < 64) rv_s[tid] = inv_norm(g_sq[2 * B_ * C_ + cb + tid]);
    for (int i = tid; i < 4096; i += 256) {
        float s = 0.f;
#pragma unroll
        for (int p = 0; p < NSPLIT; p++) s += g_part[((size_t)bh * NSPLIT + p) * 4096 + i];
        int r = i >> 6, c = i & 63;
        Ss[r][c] = s * inv_norm(g_sq[cb + r]) * scale * inv_norm(g_sq[B_ * C_ + cb + c]);
    }
    __syncthreads();
    int warp = tid >> 5, lane = tid & 31;
#pragma unroll
    for (int rr = 0; rr < 8; rr++) {
        int r = warp * 8 + rr;
        float v0 = Ss[r][lane], v1 = Ss[r][lane + 32];
        float m = fmaxf(v0, v1);
#pragma unroll
        for (int off = 16; off; off >>= 1) m = fmaxf(m, __shfl_xor_sync(0xffffffffu, m, off));
        float e0 = __expf(v0 - m), e1 = __expf(v1 - m);
        float s = e0 + e1;
#pragma unroll
        for (int off = 16; off; off >>= 1) s += __shfl_xor_sync(0xffffffffu, s, off);
        float inv = 1.0f / s;
        size_t base = (size_t)bh * 4096 + r * 64;
        g_at[base + lane]      = __float2half_rn(e0 * inv * rv_s[lane]);
        g_at[base + lane + 32] = __float2half_rn(e1 * inv * rv_s[lane + 32]);
    }
}

// ---------------- apply: fp16 HMMA out = attn @ v -> ao fp16 ----------------
#define AP_A 0
#define AP_V 8192
#define AP_SMEM 24576

__global__ __launch_bounds__(256) void apply_kernel() {
    extern __shared__ char smem[];
    uint32_t sb = smem_u32(smem);
    int ntile = blockIdx.x;
    int bh = blockIdx.y;
    int b = bh >> 3, hg = bh & 7;
    int tid = threadIdx.x, l = tid & 31, wid = tid >> 5;
    int wm = wid & 1, wn = wid >> 1;

#pragma unroll
    for (int it = 0; it < 2; it++) {
        int idx = tid + it * 256;
        int r = idx >> 3, c8 = idx & 7;
        uint32_t swo = sw128((uint32_t)(r * 128 + c8 * 16));
        CP16(sb + AP_A + swo, g_at + (size_t)bh * 4096 + r * 64 + c8 * 8);
    }
    const __half* vp = g_v + ((size_t)b * C_ + hg * HD) * NPIX + ntile * 128;
#pragma unroll
    for (int it = 0; it < 4; it++) {
        int idx = tid + it * 256;
        int r = idx >> 4;
        int n8 = idx & 15;
        int s = n8 >> 3, nl = n8 & 7;
        uint32_t swo = (uint32_t)(s * 8192) + sw128((uint32_t)(r * 128 + nl * 16));
        CP16(sb + AP_V + swo, vp + (size_t)r * NPIX + n8 * 8);
    }
    CP_COMMIT();
    CP_WAIT0();
    __syncthreads();

    float acc[2][4][4] = {};
    int lr = l & 15, lc = (l >> 4) << 4;
#pragma unroll
    for (int k16 = 0; k16 < 4; k16++) {
        uint32_t ah[2][4], bf[2][4];
#pragma unroll
        for (int mt = 0; mt < 2; mt++) {
            uint32_t swo = sw128((uint32_t)((wm * 32 + mt * 16 + lr) * 128 + k16 * 32 + lc));
            LDSM_X4(ah[mt], sb + AP_A + swo);
        }
        uint32_t pb = (uint32_t)((wn >> 1) * 8192);
#pragma unroll
        for (int h = 0; h < 2; h++) {
            uint32_t swo = sw128((uint32_t)((k16 * 16 + lr) * 128 + (wn & 1) * 64 + h * 32 + lc));
            LDSM_X4T(bf[h], sb + AP_V + pb + swo);
        }
#pragma unroll
        for (int mt = 0; mt < 2; mt++)
#pragma unroll
            for (int nt = 0; nt < 4; nt++) {
                int h = nt >> 1, pr = (nt & 1) * 2;
                MMA16816(acc[mt][nt], ah[mt], bf[h][pr], bf[h][pr + 1]);
            }
    }

    int l4 = l >> 2, l2 = (l & 3) << 1;
#pragma unroll
    for (int mt = 0; mt < 2; mt++)
#pragma unroll
        for (int half = 0; half < 2; half++) {
            int row = wm * 32 + mt * 16 + l4 + half * 8;
            __half* po = g_ao + ((size_t)b * C_ + hg * HD + row) * NPIX + ntile * 128;
#pragma unroll
            for (int nt = 0; nt < 4; nt++) {
                int col = wn * 32 + nt * 8 + l2;
                *(uint32_t*)(po + col) =
                    pack2h(__float2half_rn(acc[mt][nt][half * 2]),
                           __float2half_rn(acc[mt][nt][half * 2 + 1]));
            }
        }
}

// ---------------- launch ----------------
extern "C" void kernel_launch(void* const* d_in, const int* in_sizes, int n_in,
                              void* d_out, int out_size) {
    const float* x  = (const float*)d_in[0];
    const float* dw = (const float*)d_in[1];
    const float* qw = (const float*)d_in[2];
    const float* kw = (const float*)d_in[3];
    const float* vw = (const float*)d_in[4];
    const float* pw = (const float*)d_in[5];
    float* out = (float*)d_out;

    __half *yp, *aop, *whp;
    cudaGetSymbolAddress((void**)&yp,  g_y);
    cudaGetSymbolAddress((void**)&aop, g_ao);
    cudaGetSymbolAddress((void**)&whp, g_wh);

    cudaFuncSetAttribute(gemm1_kernel<0>, cudaFuncAttributeMaxDynamicSharedMemorySize, Q_SMEM);
    cudaFuncSetAttribute(gemm1_kernel<1>, cudaFuncAttributeMaxDynamicSharedMemorySize, Q_SMEM);
    cudaFuncSetAttribute(scores_kernel, cudaFuncAttributeMaxDynamicSharedMemorySize, SC_SMEM);
    cudaFuncSetAttribute(apply_kernel,  cudaFuncAttributeMaxDynamicSharedMemorySize, AP_SMEM);

    dwconv_kernel<<<dim3(NPIX / 256, B_ * C_), 256>>>(x, dw);              // 1
    convert_w_kernel<<<4096, 256>>>(qw, kw, vw, pw);                       // 2 (+ zero g_sq)
    // fused QKV GEMM, M=1536, CTA 128x128, 256 threads (profiled slot)
    gemm1_kernel<0><<<dim3(NPIX / 128, 12, B_), 256, Q_SMEM>>>(whp, yp, nullptr); // 3
    scores_kernel<<<dim3(NSPLIT, B_ * HEADS_), 256, SC_SMEM>>>();          // 4
    softmax_kernel<<<B_ * HEADS_, 256>>>();                                // 5
    apply_kernel<<<dim3(NPIX / 128, B_ * HEADS_), 256, AP_SMEM>>>();       // 6
    // proj GEMM: 1-term, CTA 128x128, 256 threads, weight rows [1536, 2048)
    gemm1_kernel<1><<<dim3(NPIX / 128, 4, B_), 256, Q_SMEM>>>(             // 7
        whp + 1536 * C_, aop, out);
}

// round 13
// speedup vs baseline: 1.4753x; 1.0046x over previous
#include <cuda_runtime.h>
#include <cuda_fp16.h>
#include <math.h>
#include <stdint.h>

#define B_     8
#define C_     512
#define HH     64
#define WW     64
#define NPIX   4096
#define HEADS_ 8
#define HD     64
#define TOFF   (B_ * C_ * NPIX)
#define NSPLIT 16

// ---------------- scratch ----------------
__device__ __align__(16) __half g_y [TOFF];
__device__ __align__(16) __half g_q [TOFF], g_k[TOFF], g_v[TOFF];
__device__ __align__(16) __half g_ao[TOFF];
__device__ __align__(16) __half g_wh[4 * C_ * C_];
__device__ __align__(16) __half g_at[B_ * HEADS_ * HD * HD];
__device__ float g_part[B_ * HEADS_ * NSPLIT * HD * HD];
__device__ float g_sq[3 * B_ * C_];
__device__ int   g_cnt[B_ * HEADS_];

// ---------------- PTX helpers (baseline sm_80+) ----------------
__device__ __forceinline__ uint32_t smem_u32(const void* p) {
    uint32_t a;
    asm("{ .reg .u64 t; cvta.to.shared.u64 t, %1; cvt.u32.u64 %0, t; }" : "=r"(a) : "l"(p));
    return a;
}
#define CP16(s, g) asm volatile("cp.async.cg.shared.global [%0], [%1], 16;" :: "r"(s), "l"(g))
#define CP_COMMIT() asm volatile("cp.async.commit_group;" ::: "memory")
#define CP_WAIT(n)  asm volatile("cp.async.wait_group %0;" :: "n"(n) : "memory")
#define CP_WAIT0()  asm volatile("cp.async.wait_group 0;" ::: "memory")

#define LDSM_X4(r, a) \
    asm volatile("ldmatrix.sync.aligned.m8n8.x4.shared.b16 {%0,%1,%2,%3}, [%4];" \
        : "=r"((r)[0]), "=r"((r)[1]), "=r"((r)[2]), "=r"((r)[3]) : "r"(a))
#define LDSM_X4T(r, a) \
    asm volatile("ldmatrix.sync.aligned.m8n8.x4.trans.shared.b16 {%0,%1,%2,%3}, [%4];" \
        : "=r"((r)[0]), "=r"((r)[1]), "=r"((r)[2]), "=r"((r)[3]) : "r"(a))
#define MMA16816(d, a, b0, b1) \
    asm volatile("mma.sync.aligned.m16n8k16.row.col.f32.f16.f16.f32 " \
        "{%0,%1,%2,%3}, {%4,%5,%6,%7}, {%8,%9}, {%0,%1,%2,%3};" \
        : "+f"((d)[0]), "+f"((d)[1]), "+f"((d)[2]), "+f"((d)[3]) \
        : "r"((a)[0]), "r"((a)[1]), "r"((a)[2]), "r"((a)[3]), "r"(b0), "r"(b1))

__device__ __forceinline__ uint32_t sw128(uint32_t o) { return o ^ ((o >> 3) & 0x70); }

__device__ __forceinline__ uint32_t pack2h(__half a, __half b) {
    unsigned short ua = *(unsigned short*)&a, ub = *(unsigned short*)&b;
    return (uint32_t)ua | ((uint32_t)ub << 16);
}
__device__ __forceinline__ float inv_norm(float s) {
    return 1.0f / fmaxf(sqrtf(s), 1e-12f);
}

// ---------------- fused: depthwise 3x3 -> fp16 | weight convert + zero ----------------
__global__ __launch_bounds__(256) void prep_kernel(const float* __restrict__ x,
                                                   const float* __restrict__ w,
                                                   const float* __restrict__ qw,
                                                   const float* __restrict__ kw,
                                                   const float* __restrict__ vw,
                                                   const float* __restrict__ pw) {
    if (blockIdx.y < 4096) {
        // ---- dwconv path ----
        int plane = blockIdx.y;
        int c = plane & (C_ - 1);
        __shared__ float ws[9];
        if (threadIdx.x < 9) ws[threadIdx.x] = w[c * 9 + threadIdx.x];
        __syncthreads();
        int p = blockIdx.x * 256 + threadIdx.x;
        int h = p >> 6, wc = p & 63;
        const float* xp = x + (size_t)plane * NPIX;
        float acc = 0.f;
#pragma unroll
        for (int kh = 0; kh < 3; kh++) {
            int hh = h + kh - 1;
            if (hh < 0 || hh >= HH) continue;
#pragma unroll
            for (int kw2 = 0; kw2 < 3; kw2++) {
                int wcol = wc + kw2 - 1;
                if (wcol < 0 || wcol >= WW) continue;
                acc = fmaf(ws[kh * 3 + kw2], xp[hh * WW + wcol], acc);
            }
        }
        g_y[(size_t)plane * NPIX + p] = __float2half_rn(acc);
    } else {
        // ---- weight convert + zero path ----
        int cb = (blockIdx.y - 4096) * 16 + blockIdx.x;   // 0..4095
        int idx = cb * 256 + threadIdx.x;
        if (cb < 48) {
            int zi = cb * 256 + threadIdx.x;
            if (zi < 3 * B_ * C_) g_sq[zi] = 0.f;
        }
        if (cb == 48 && threadIdx.x < B_ * HEADS_) g_cnt[threadIdx.x] = 0;
        int m = idx >> 18;
        const float* src = (m == 0) ? qw : (m == 1) ? kw : (m == 2) ? vw : pw;
        g_wh[idx] = __float2half_rn(src[idx & 262143]);
    }
}

// ---------------- 1-term fp16 GEMM, CTA 128x128, 256 threads, 3-stage ----------------
// OUTMODE 0: write q/k/v fp16 + per-row sumsq. OUTMODE 1: write fp32 Cout.
#define Q_A 0
#define Q_B 16384
#define Q_STAGE 32768
#define Q_SMEM (3 * Q_STAGE)

template <int OUTMODE>
__global__ __launch_bounds__(256, 2) void gemm1_kernel(const __half* __restrict__ Wh,
                                                       const __half* __restrict__ Bg,
                                                       float* __restrict__ Cout) {
    extern __shared__ char smem[];
    uint32_t sb = smem_u32(smem);
    int tid = threadIdx.x;
    int l = tid & 31, wid = tid >> 5;
    int wm = wid & 3, wn = wid >> 2;        // warp tile: 32 rows x 64 cols
    int bn = blockIdx.x * 128;
    int bm = blockIdx.y * 128;
    int bz = blockIdx.z;
    const __half* Bp = Bg + (size_t)bz * C_ * NPIX;

    auto load_chunk = [&](int chunk, int stg) {
        uint32_t st = sb + stg * Q_STAGE;
        int k0 = chunk * 64;
#pragma unroll
        for (int it = 0; it < 4; it++) {
            int idx = tid + it * 256;              // 0..1023
            int ar = idx >> 3;                     // 0..127
            int ac = (idx & 7) << 3;
            uint32_t aswo = sw128((uint32_t)(ar * 128 + ac * 2));
            CP16(st + Q_A + aswo, Wh + (size_t)(bm + ar) * C_ + k0 + ac);
            int brr = idx >> 4;                    // 0..63
            int bnn = (idx & 15) << 3;             // 0..120
            int s = bnn >> 6, nl = bnn & 63;
            uint32_t bswo = (uint32_t)(s * 8192) + sw128((uint32_t)(brr * 128 + nl * 2));
            CP16(st + Q_B + bswo, Bp + (size_t)(k0 + brr) * NPIX + bn + bnn);
        }
    };

    float acc[2][8][4] = {};
    int lr = l & 15;
    int lc = (l >> 4) << 4;

    load_chunk(0, 0); CP_COMMIT();
    load_chunk(1, 1); CP_COMMIT();

    for (int chunk = 0; chunk < 8; chunk++) {
        CP_WAIT(1);
        __syncthreads();
        uint32_t st = sb + (chunk % 3) * Q_STAGE;
#pragma unroll
        for (int k16 = 0; k16 < 4; k16++) {
            uint32_t ah[2][4], bf[4][4];
#pragma unroll
            for (int mt = 0; mt < 2; mt++) {
                uint32_t swo = sw128((uint32_t)((wm * 32 + mt * 16 + lr) * 128 + k16 * 32 + lc));
                LDSM_X4(ah[mt], st + Q_A + swo);
            }
            uint32_t pb = (uint32_t)(wn * 8192);
#pragma unroll
            for (int h = 0; h < 4; h++) {
                uint32_t swo = sw128((uint32_t)((k16 * 16 + lr) * 128 + h * 32 + lc));
                LDSM_X4T(bf[h], st + Q_B + pb + swo);
            }
#pragma unroll
            for (int mt = 0; mt < 2; mt++)
#pragma unroll
                for (int nt = 0; nt < 8; nt++) {
                    int h = nt >> 1, pr = (nt & 1) * 2;
                    MMA16816(acc[mt][nt], ah[mt], bf[h][pr], bf[h][pr + 1]);
                }
        }
        __syncthreads();
        if (chunk + 2 < 8) load_chunk(chunk + 2, (chunk + 2) % 3);
        CP_COMMIT();
    }

    int l4 = l >> 2, l2 = (l & 3) << 1;
    if (OUTMODE == 0) {
#pragma unroll
        for (int mt = 0; mt < 2; mt++) {
#pragma unroll
            for (int half = 0; half < 2; half++) {
                int row = bm + wm * 32 + mt * 16 + l4 + half * 8;
                int which = row >> 9, ml = row & 511;
                __half* pq = ((which == 0) ? g_q : (which == 1) ? g_k : g_v)
                             + ((size_t)bz * C_ + ml) * NPIX;
                float ss = 0.f;
#pragma unroll
                for (int nt = 0; nt < 8; nt++) {
                    int col = bn + wn * 64 + nt * 8 + l2;
                    float v0 = acc[mt][nt][half * 2], v1 = acc[mt][nt][half * 2 + 1];
                    ss += v0 * v0 + v1 * v1;
                    *(uint32_t*)(pq + col) = pack2h(__float2half_rn(v0), __float2half_rn(v1));
                }
                ss += __shfl_xor_sync(0xffffffffu, ss, 1);
                ss += __shfl_xor_sync(0xffffffffu, ss, 2);
                if ((l & 3) == 0)
                    atomicAdd(&g_sq[which * (B_ * C_) + bz * C_ + ml], ss);
            }
        }
    } else {
#pragma unroll
        for (int mt = 0; mt < 2; mt++) {
#pragma unroll
            for (int half = 0; half < 2; half++) {
                int row = bm + wm * 32 + mt * 16 + l4 + half * 8;
                float* base = Cout + ((size_t)bz * C_ + row) * NPIX;
#pragma unroll
                for (int nt = 0; nt < 8; nt++) {
                    int col = bn + wn * 64 + nt * 8 + l2;
                    *(float2*)(base + col) =
                        make_float2(acc[mt][nt][half * 2], acc[mt][nt][half * 2 + 1]);
                }
            }
        }
    }
}

// ---------------- scores + fused softmax (threadfence reduction) ----------------
#define SC_Q 0
#define SC_K 8192
#define SC_STAGE 16384
#define SC_SMEM (2 * SC_STAGE)    // 32 KB; softmax reuse needs 64*64*4 + 256 = 16.6 KB

__global__ __launch_bounds__(256) void scores_kernel() {
    extern __shared__ char smem[];
    uint32_t sb = smem_u32(smem);
    int sp = blockIdx.x, bh = blockIdx.y;
    int b = bh >> 3, hg = bh & 7;
    int tid = threadIdx.x, l = tid & 31, wid = tid >> 5;
    int wm = wid & 1, wn = wid >> 1;
    const __half* qp = g_q + ((size_t)b * C_ + hg * HD) * NPIX;
    const __half* kp = g_k + ((size_t)b * C_ + hg * HD) * NPIX;
    int px0 = sp * 256;

    auto load_chunk = [&](int chunk, int stg) {
        uint32_t st = sb + stg * SC_STAGE;
        int k0 = px0 + chunk * 64;
#pragma unroll
        for (int it = 0; it < 2; it++) {
            int idx = tid + it * 256;
            int r = idx >> 3;
            int c8 = idx & 7;
            uint32_t swo = sw128((uint32_t)(r * 128 + c8 * 16));
            size_t go = (size_t)r * NPIX + k0 + c8 * 8;
            CP16(st + SC_Q + swo, qp + go);
            CP16(st + SC_K + swo, kp + go);
        }
    };

    float acc[2][2][4] = {};
    int lr = l & 15, lc = (l >> 4) << 4;
    int bn_row = wn * 16 + (l & 7) + ((l >> 4) << 3);
    int bn_kb = ((l >> 3) & 1) * 16;

    load_chunk(0, 0); CP_COMMIT();
    load_chunk(1, 1); CP_COMMIT();

    for (int chunk = 0; chunk < 4; chunk++) {
        CP_WAIT(1);
        __syncthreads();
        uint32_t st = sb + (chunk & 1) * SC_STAGE;
#pragma unroll
        for (int k16 = 0; k16 < 4; k16++) {
            uint32_t ah[2][4], bf[4];
#pragma unroll
            for (int mt = 0; mt < 2; mt++) {
                uint32_t swo = sw128((uint32_t)((wm * 32 + mt * 16 + lr) * 128 + k16 * 32 + lc));
                LDSM_X4(ah[mt], st + SC_Q + swo);
            }
            uint32_t swb = sw128((uint32_t)(bn_row * 128 + k16 * 32 + bn_kb));
            LDSM_X4(bf, st + SC_K + swb);
#pragma unroll
            for (int mt = 0; mt < 2; mt++)
#pragma unroll
                for (int nt = 0; nt < 2; nt++)
                    MMA16816(acc[mt][nt], ah[mt], bf[nt * 2], bf[nt * 2 + 1]);
        }
        __syncthreads();
        if (chunk + 2 < 4) load_chunk(chunk + 2, chunk & 1);
        CP_COMMIT();
    }

    float* op = g_part + ((size_t)bh * NSPLIT + sp) * 4096;
    int l4 = l >> 2, l2 = (l & 3) << 1;
#pragma unroll
    for (int mt = 0; mt < 2; mt++)
#pragma unroll
        for (int half = 0; half < 2; half++) {
            int row = wm * 32 + mt * 16 + l4 + half * 8;
#pragma unroll
            for (int nt = 0; nt < 2; nt++) {
                int col = wn * 16 + nt * 8 + l2;
                *(float2*)(op + row * 64 + col) =
                    make_float2(acc[mt][nt][half * 2], acc[mt][nt][half * 2 + 1]);
            }
        }

    // ---- fused softmax: last CTA per bh reduces partials ----
    __syncthreads();
    __threadfence();
    __shared__ int is_last;
    if (tid == 0) {
        int old = atomicAdd(&g_cnt[bh], 1);
        is_last = (old == NSPLIT - 1) ? 1 : 0;
    }
    __syncthreads();
    if (!is_last) return;
    __threadfence();   // acquire: see all partials

    float* Ss = (float*)smem;                 // 64x64 fp32 = 16 KB
    float* rv_s = (float*)(smem + 16384);     // 64 fp32
    int cb = b * C_ + hg * HD;
    const float scale = 0.125f;
    if (tid < 64) rv_s[tid] = inv_norm(g_sq[2 * B_ * C_ + cb + tid]);
    for (int i = tid; i < 4096; i += 256) {
        float s = 0.f;
#pragma unroll
        for (int p = 0; p < NSPLIT; p++) s += g_part[((size_t)bh * NSPLIT + p) * 4096 + i];
        int r = i >> 6, c = i & 63;
        Ss[r * 64 + c] = s * inv_norm(g_sq[cb + r]) * scale * inv_norm(g_sq[B_ * C_ + cb + c]);
    }
    __syncthreads();
    int warp = tid >> 5, lane = tid & 31;
#pragma unroll
    for (int rr = 0; rr < 8; rr++) {
        int r = warp * 8 + rr;
        float v0 = Ss[r * 64 + lane], v1 = Ss[r * 64 + lane + 32];
        float m = fmaxf(v0, v1);
#pragma unroll
        for (int off = 16; off; off >>= 1) m = fmaxf(m, __shfl_xor_sync(0xffffffffu, m, off));
        float e0 = __expf(v0 - m), e1 = __expf(v1 - m);
        float s = e0 + e1;
#pragma unroll
        for (int off = 16; off; off >>= 1) s += __shfl_xor_sync(0xffffffffu, s, off);
        float inv = 1.0f / s;
        size_t base = (size_t)bh * 4096 + r * 64;
        g_at[base + lane]      = __float2half_rn(e0 * inv * rv_s[lane]);
        g_at[base + lane + 32] = __float2half_rn(e1 * inv * rv_s[lane + 32]);
    }
}

// ---------------- apply: fp16 HMMA out = attn @ v -> ao fp16 ----------------
#define AP_A 0
#define AP_V 8192
#define AP_SMEM 24576

__global__ __launch_bounds__(256) void apply_kernel() {
    extern __shared__ char smem[];
    uint32_t sb = smem_u32(smem);
    int ntile = blockIdx.x;
    int bh = blockIdx.y;
    int b = bh >> 3, hg = bh & 7;
    int tid = threadIdx.x, l = tid & 31, wid = tid >> 5;
    int wm = wid & 1, wn = wid >> 1;

#pragma unroll
    for (int it = 0; it < 2; it++) {
        int idx = tid + it * 256;
        int r = idx >> 3, c8 = idx & 7;
        uint32_t swo = sw128((uint32_t)(r * 128 + c8 * 16));
        CP16(sb + AP_A + swo, g_at + (size_t)bh * 4096 + r * 64 + c8 * 8);
    }
    const __half* vp = g_v + ((size_t)b * C_ + hg * HD) * NPIX + ntile * 128;
#pragma unroll
    for (int it = 0; it < 4; it++) {
        int idx = tid + it * 256;
        int r = idx >> 4;
        int n8 = idx & 15;
        int s = n8 >> 3, nl = n8 & 7;
        uint32_t swo = (uint32_t)(s * 8192) + sw128((uint32_t)(r * 128 + nl * 16));
        CP16(sb + AP_V + swo, vp + (size_t)r * NPIX + n8 * 8);
    }
    CP_COMMIT();
    CP_WAIT0();
    __syncthreads();

    float acc[2][4][4] = {};
    int lr = l & 15, lc = (l >> 4) << 4;
#pragma unroll
    for (int k16 = 0; k16 < 4; k16++) {
        uint32_t ah[2][4], bf[2][4];
#pragma unroll
        for (int mt = 0; mt < 2; mt++) {
            uint32_t swo = sw128((uint32_t)((wm * 32 + mt * 16 + lr) * 128 + k16 * 32 + lc));
            LDSM_X4(ah[mt], sb + AP_A + swo);
        }
        uint32_t pb = (uint32_t)((wn >> 1) * 8192);
#pragma unroll
        for (int h = 0; h < 2; h++) {
            uint32_t swo = sw128((uint32_t)((k16 * 16 + lr) * 128 + (wn & 1) * 64 + h * 32 + lc));
            LDSM_X4T(bf[h], sb + AP_V + pb + swo);
        }
#pragma unroll
        for (int mt = 0; mt < 2; mt++)
#pragma unroll
            for (int nt = 0; nt < 4; nt++) {
                int h = nt >> 1, pr = (nt & 1) * 2;
                MMA16816(acc[mt][nt], ah[mt], bf[h][pr], bf[h][pr + 1]);
            }
    }

    int l4 = l >> 2, l2 = (l & 3) << 1;
#pragma unroll
    for (int mt = 0; mt < 2; mt++)
#pragma unroll
        for (int half = 0; half < 2; half++) {
            int row = wm * 32 + mt * 16 + l4 + half * 8;
            __half* po = g_ao + ((size_t)b * C_ + hg * HD + row) * NPIX + ntile * 128;
#pragma unroll
            for (int nt = 0; nt < 4; nt++) {
                int col = wn * 32 + nt * 8 + l2;
                *(uint32_t*)(po + col) =
                    pack2h(__float2half_rn(acc[mt][nt][half * 2]),
                           __float2half_rn(acc[mt][nt][half * 2 + 1]));
            }
        }
}

// ---------------- launch ----------------
extern "C" void kernel_launch(void* const* d_in, const int* in_sizes, int n_in,
                              void* d_out, int out_size) {
    const float* x  = (const float*)d_in[0];
    const float* dw = (const float*)d_in[1];
    const float* qw = (const float*)d_in[2];
    const float* kw = (const float*)d_in[3];
    const float* vw = (const float*)d_in[4];
    const float* pw = (const float*)d_in[5];
    float* out = (float*)d_out;

    __half *yp, *aop, *whp;
    cudaGetSymbolAddress((void**)&yp,  g_y);
    cudaGetSymbolAddress((void**)&aop, g_ao);
    cudaGetSymbolAddress((void**)&whp, g_wh);

    cudaFuncSetAttribute(gemm1_kernel<0>, cudaFuncAttributeMaxDynamicSharedMemorySize, Q_SMEM);
    cudaFuncSetAttribute(gemm1_kernel<1>, cudaFuncAttributeMaxDynamicSharedMemorySize, Q_SMEM);
    cudaFuncSetAttribute(scores_kernel, cudaFuncAttributeMaxDynamicSharedMemorySize, SC_SMEM);
    cudaFuncSetAttribute(apply_kernel,  cudaFuncAttributeMaxDynamicSharedMemorySize, AP_SMEM);

    // 1: dwconv + weight convert + zero counters (fused)
    prep_kernel<<<dim3(16, 4096 + 256), 256>>>(x, dw, qw, kw, vw, pw);
    // 2: fused QKV GEMM, M=1536, CTA 128x128
    gemm1_kernel<0><<<dim3(NPIX / 128, 12, B_), 256, Q_SMEM>>>(whp, yp, nullptr);
    // 3: scores + fused softmax
    scores_kernel<<<dim3(NSPLIT, B_ * HEADS_), 256, SC_SMEM>>>();
    // 4: apply
    apply_kernel<<<dim3(NPIX / 128, B_ * HEADS_), 256, AP_SMEM>>>();
    // 5: proj GEMM (1-term, weight rows [1536, 2048))
    gemm1_kernel<1><<<dim3(NPIX / 128, 4, B_), 256, Q_SMEM>>>(whp + 1536 * C_, aop, out);
}

// round 14
// speedup vs baseline: 1.5335x; 1.0394x over previous
#include <cuda_runtime.h>
#include <cuda_fp16.h>
#include <math.h>
#include <stdint.h>

#define B_     8
#define C_     512
#define HH     64
#define WW     64
#define NPIX   4096
#define HEADS_ 8
#define HD     64
#define TOFF   (B_ * C_ * NPIX)
#define NSPLIT 16

// ---------------- scratch ----------------
__device__ __align__(16) __half g_y [TOFF];
__device__ __align__(16) __half g_q [TOFF], g_k[TOFF], g_v[TOFF];
__device__ __align__(16) __half g_wh[4 * C_ * C_];
__device__ __align__(16) __half g_wp[B_ * C_ * C_];       // per-batch effective proj weight
__device__ __align__(16) __half g_at[B_ * HEADS_ * HD * HD];
__device__ float g_part[B_ * HEADS_ * NSPLIT * HD * HD];
__device__ float g_sq[3 * B_ * C_];
__device__ int   g_cnt[B_ * HEADS_];

// ---------------- PTX helpers (baseline sm_80+) ----------------
__device__ __forceinline__ uint32_t smem_u32(const void* p) {
    uint32_t a;
    asm("{ .reg .u64 t; cvta.to.shared.u64 t, %1; cvt.u32.u64 %0, t; }" : "=r"(a) : "l"(p));
    return a;
}
#define CP16(s, g) asm volatile("cp.async.cg.shared.global [%0], [%1], 16;" :: "r"(s), "l"(g))
#define CP_COMMIT() asm volatile("cp.async.commit_group;" ::: "memory")
#define CP_WAIT(n)  asm volatile("cp.async.wait_group %0;" :: "n"(n) : "memory")
#define CP_WAIT0()  asm volatile("cp.async.wait_group 0;" ::: "memory")

#define LDSM_X4(r, a) \
    asm volatile("ldmatrix.sync.aligned.m8n8.x4.shared.b16 {%0,%1,%2,%3}, [%4];" \
        : "=r"((r)[0]), "=r"((r)[1]), "=r"((r)[2]), "=r"((r)[3]) : "r"(a))
#define LDSM_X4T(r, a) \
    asm volatile("ldmatrix.sync.aligned.m8n8.x4.trans.shared.b16 {%0,%1,%2,%3}, [%4];" \
        : "=r"((r)[0]), "=r"((r)[1]), "=r"((r)[2]), "=r"((r)[3]) : "r"(a))
#define MMA16816(d, a, b0, b1) \
    asm volatile("mma.sync.aligned.m16n8k16.row.col.f32.f16.f16.f32 " \
        "{%0,%1,%2,%3}, {%4,%5,%6,%7}, {%8,%9}, {%0,%1,%2,%3};" \
        : "+f"((d)[0]), "+f"((d)[1]), "+f"((d)[2]), "+f"((d)[3]) \
        : "r"((a)[0]), "r"((a)[1]), "r"((a)[2]), "r"((a)[3]), "r"(b0), "r"(b1))

__device__ __forceinline__ uint32_t sw128(uint32_t o) { return o ^ ((o >> 3) & 0x70); }

__device__ __forceinline__ uint32_t pack2h(__half a, __half b) {
    unsigned short ua = *(unsigned short*)&a, ub = *(unsigned short*)&b;
    return (uint32_t)ua | ((uint32_t)ub << 16);
}
__device__ __forceinline__ float inv_norm(float s) {
    return 1.0f / fmaxf(sqrtf(s), 1e-12f);
}

// ---------------- fused: depthwise 3x3 -> fp16 | weight convert + zero ----------------
__global__ __launch_bounds__(256) void prep_kernel(const float* __restrict__ x,
                                                   const float* __restrict__ w,
                                                   const float* __restrict__ qw,
                                                   const float* __restrict__ kw,
                                                   const float* __restrict__ vw,
                                                   const float* __restrict__ pw) {
    if (blockIdx.y < 4096) {
        int plane = blockIdx.y;
        int c = plane & (C_ - 1);
        __shared__ float ws[9];
        if (threadIdx.x < 9) ws[threadIdx.x] = w[c * 9 + threadIdx.x];
        __syncthreads();
        int p = blockIdx.x * 256 + threadIdx.x;
        int h = p >> 6, wc = p & 63;
        const float* xp = x + (size_t)plane * NPIX;
        float acc = 0.f;
#pragma unroll
        for (int kh = 0; kh < 3; kh++) {
            int hh = h + kh - 1;
            if (hh < 0 || hh >= HH) continue;
#pragma unroll
            for (int kw2 = 0; kw2 < 3; kw2++) {
                int wcol = wc + kw2 - 1;
                if (wcol < 0 || wcol >= WW) continue;
                acc = fmaf(ws[kh * 3 + kw2], xp[hh * WW + wcol], acc);
            }
        }
        g_y[(size_t)plane * NPIX + p] = __float2half_rn(acc);
    } else {
        int cb = (blockIdx.y - 4096) * 16 + blockIdx.x;   // 0..4095
        int idx = cb * 256 + threadIdx.x;
        if (cb < 48) {
            int zi = cb * 256 + threadIdx.x;
            if (zi < 3 * B_ * C_) g_sq[zi] = 0.f;
        }
        if (cb == 48 && threadIdx.x < B_ * HEADS_) g_cnt[threadIdx.x] = 0;
        int m = idx >> 18;
        const float* src = (m == 0) ? qw : (m == 1) ? kw : (m == 2) ? vw : pw;
        g_wh[idx] = __float2half_rn(src[idx & 262143]);
    }
}

// ---------------- 1-term fp16 GEMM, CTA 128x128, 256 threads, 3-stage ----------------
// OUTMODE 0: write q/k/v fp16 + per-row sumsq. OUTMODE 1: write fp32 Cout.
// ABATCH 1: A operand is per-batch (stride C_*C_).
#define Q_A 0
#define Q_B 16384
#define Q_STAGE 32768
#define Q_SMEM (3 * Q_STAGE)

template <int OUTMODE, int ABATCH>
__global__ __launch_bounds__(256, 2) void gemm1_kernel(const __half* __restrict__ Wh,
                                                       const __half* __restrict__ Bg,
                                                       float* __restrict__ Cout) {
    extern __shared__ char smem[];
    uint32_t sb = smem_u32(smem);
    int tid = threadIdx.x;
    int l = tid & 31, wid = tid >> 5;
    int wm = wid & 3, wn = wid >> 2;        // warp tile: 32 rows x 64 cols
    int bn = blockIdx.x * 128;
    int bm = blockIdx.y * 128;
    int bz = blockIdx.z;
    const __half* Ap = Wh + (ABATCH ? (size_t)bz * C_ * C_ : 0);
    const __half* Bp = Bg + (size_t)bz * C_ * NPIX;

    auto load_chunk = [&](int chunk, int stg) {
        uint32_t st = sb + stg * Q_STAGE;
        int k0 = chunk * 64;
#pragma unroll
        for (int it = 0; it < 4; it++) {
            int idx = tid + it * 256;              // 0..1023
            int ar = idx >> 3;                     // 0..127
            int ac = (idx & 7) << 3;
            uint32_t aswo = sw128((uint32_t)(ar * 128 + ac * 2));
            CP16(st + Q_A + aswo, Ap + (size_t)(bm + ar) * C_ + k0 + ac);
            int brr = idx >> 4;                    // 0..63
            int bnn = (idx & 15) << 3;             // 0..120
            int s = bnn >> 6, nl = bnn & 63;
            uint32_t bswo = (uint32_t)(s * 8192) + sw128((uint32_t)(brr * 128 + nl * 2));
            CP16(st + Q_B + bswo, Bp + (size_t)(k0 + brr) * NPIX + bn + bnn);
        }
    };

    float acc[2][8][4] = {};
    int lr = l & 15;
    int lc = (l >> 4) << 4;

    load_chunk(0, 0); CP_COMMIT();
    load_chunk(1, 1); CP_COMMIT();

    for (int chunk = 0; chunk < 8; chunk++) {
        CP_WAIT(1);
        __syncthreads();
        uint32_t st = sb + (chunk % 3) * Q_STAGE;
#pragma unroll
        for (int k16 = 0; k16 < 4; k16++) {
            uint32_t ah[2][4], bf[4][4];
#pragma unroll
            for (int mt = 0; mt < 2; mt++) {
                uint32_t swo = sw128((uint32_t)((wm * 32 + mt * 16 + lr) * 128 + k16 * 32 + lc));
                LDSM_X4(ah[mt], st + Q_A + swo);
            }
            uint32_t pb = (uint32_t)(wn * 8192);
#pragma unroll
            for (int h = 0; h < 4; h++) {
                uint32_t swo = sw128((uint32_t)((k16 * 16 + lr) * 128 + h * 32 + lc));
                LDSM_X4T(bf[h], st + Q_B + pb + swo);
            }
#pragma unroll
            for (int mt = 0; mt < 2; mt++)
#pragma unroll
                for (int nt = 0; nt < 8; nt++) {
                    int h = nt >> 1, pr = (nt & 1) * 2;
                    MMA16816(acc[mt][nt], ah[mt], bf[h][pr], bf[h][pr + 1]);
                }
        }
        __syncthreads();
        if (chunk + 2 < 8) load_chunk(chunk + 2, (chunk + 2) % 3);
        CP_COMMIT();
    }

    int l4 = l >> 2, l2 = (l & 3) << 1;
    if (OUTMODE == 0) {
#pragma unroll
        for (int mt = 0; mt < 2; mt++) {
#pragma unroll
            for (int half = 0; half < 2; half++) {
                int row = bm + wm * 32 + mt * 16 + l4 + half * 8;
                int which = row >> 9, ml = row & 511;
                __half* pq = ((which == 0) ? g_q : (which == 1) ? g_k : g_v)
                             + ((size_t)bz * C_ + ml) * NPIX;
                float ss = 0.f;
#pragma unroll
                for (int nt = 0; nt < 8; nt++) {
                    int col = bn + wn * 64 + nt * 8 + l2;
                    float v0 = acc[mt][nt][half * 2], v1 = acc[mt][nt][half * 2 + 1];
                    ss += v0 * v0 + v1 * v1;
                    *(uint32_t*)(pq + col) = pack2h(__float2half_rn(v0), __float2half_rn(v1));
                }
                ss += __shfl_xor_sync(0xffffffffu, ss, 1);
                ss += __shfl_xor_sync(0xffffffffu, ss, 2);
                if ((l & 3) == 0)
                    atomicAdd(&g_sq[which * (B_ * C_) + bz * C_ + ml], ss);
            }
        }
    } else {
#pragma unroll
        for (int mt = 0; mt < 2; mt++) {
#pragma unroll
            for (int half = 0; half < 2; half++) {
                int row = bm + wm * 32 + mt * 16 + l4 + half * 8;
                float* base = Cout + ((size_t)bz * C_ + row) * NPIX;
#pragma unroll
                for (int nt = 0; nt < 8; nt++) {
                    int col = bn + wn * 64 + nt * 8 + l2;
                    *(float2*)(base + col) =
                        make_float2(acc[mt][nt][half * 2], acc[mt][nt][half * 2 + 1]);
                }
            }
        }
    }
}

// ---------------- scores + fused softmax (threadfence reduction) ----------------
#define SC_Q 0
#define SC_K 8192
#define SC_STAGE 16384
#define SC_SMEM (2 * SC_STAGE)

__global__ __launch_bounds__(256) void scores_kernel() {
    extern __shared__ char smem[];
    uint32_t sb = smem_u32(smem);
    int sp = blockIdx.x, bh = blockIdx.y;
    int b = bh >> 3, hg = bh & 7;
    int tid = threadIdx.x, l = tid & 31, wid = tid >> 5;
    int wm = wid & 1, wn = wid >> 1;
    const __half* qp = g_q + ((size_t)b * C_ + hg * HD) * NPIX;
    const __half* kp = g_k + ((size_t)b * C_ + hg * HD) * NPIX;
    int px0 = sp * 256;

    auto load_chunk = [&](int chunk, int stg) {
        uint32_t st = sb + stg * SC_STAGE;
        int k0 = px0 + chunk * 64;
#pragma unroll
        for (int it = 0; it < 2; it++) {
            int idx = tid + it * 256;
            int r = idx >> 3;
            int c8 = idx & 7;
            uint32_t swo = sw128((uint32_t)(r * 128 + c8 * 16));
            size_t go = (size_t)r * NPIX + k0 + c8 * 8;
            CP16(st + SC_Q + swo, qp + go);
            CP16(st + SC_K + swo, kp + go);
        }
    };

    float acc[2][2][4] = {};
    int lr = l & 15, lc = (l >> 4) << 4;
    int bn_row = wn * 16 + (l & 7) + ((l >> 4) << 3);
    int bn_kb = ((l >> 3) & 1) * 16;

    load_chunk(0, 0); CP_COMMIT();
    load_chunk(1, 1); CP_COMMIT();

    for (int chunk = 0; chunk < 4; chunk++) {
        CP_WAIT(1);
        __syncthreads();
        uint32_t st = sb + (chunk & 1) * SC_STAGE;
#pragma unroll
        for (int k16 = 0; k16 < 4; k16++) {
            uint32_t ah[2][4], bf[4];
#pragma unroll
            for (int mt = 0; mt < 2; mt++) {
                uint32_t swo = sw128((uint32_t)((wm * 32 + mt * 16 + lr) * 128 + k16 * 32 + lc));
                LDSM_X4(ah[mt], st + SC_Q + swo);
            }
            uint32_t swb = sw128((uint32_t)(bn_row * 128 + k16 * 32 + bn_kb));
            LDSM_X4(bf, st + SC_K + swb);
#pragma unroll
            for (int mt = 0; mt < 2; mt++)
#pragma unroll
                for (int nt = 0; nt < 2; nt++)
                    MMA16816(acc[mt][nt], ah[mt], bf[nt * 2], bf[nt * 2 + 1]);
        }
        __syncthreads();
        if (chunk + 2 < 4) load_chunk(chunk + 2, chunk & 1);
        CP_COMMIT();
    }

    float* op = g_part + ((size_t)bh * NSPLIT + sp) * 4096;
    int l4 = l >> 2, l2 = (l & 3) << 1;
#pragma unroll
    for (int mt = 0; mt < 2; mt++)
#pragma unroll
        for (int half = 0; half < 2; half++) {
            int row = wm * 32 + mt * 16 + l4 + half * 8;
#pragma unroll
            for (int nt = 0; nt < 2; nt++) {
                int col = wn * 16 + nt * 8 + l2;
                *(float2*)(op + row * 64 + col) =
                    make_float2(acc[mt][nt][half * 2], acc[mt][nt][half * 2 + 1]);
            }
        }

    // ---- fused softmax: last CTA per bh reduces partials ----
    __syncthreads();
    __threadfence();
    __shared__ int is_last;
    if (tid == 0) {
        int old = atomicAdd(&g_cnt[bh], 1);
        is_last = (old == NSPLIT - 1) ? 1 : 0;
    }
    __syncthreads();
    if (!is_last) return;
    __threadfence();

    float* Ss = (float*)smem;
    float* rv_s = (float*)(smem + 16384);
    int cb = b * C_ + hg * HD;
    const float scale = 0.125f;
    if (tid < 64) rv_s[tid] = inv_norm(g_sq[2 * B_ * C_ + cb + tid]);
    for (int i = tid; i < 4096; i += 256) {
        float s = 0.f;
#pragma unroll
        for (int p = 0; p < NSPLIT; p++) s += g_part[((size_t)bh * NSPLIT + p) * 4096 + i];
        int r = i >> 6, c = i & 63;
        Ss[r * 64 + c] = s * inv_norm(g_sq[cb + r]) * scale * inv_norm(g_sq[B_ * C_ + cb + c]);
    }
    __syncthreads();
    int warp = tid >> 5, lane = tid & 31;
#pragma unroll
    for (int rr = 0; rr < 8; rr++) {
        int r = warp * 8 + rr;
        float v0 = Ss[r * 64 + lane], v1 = Ss[r * 64 + lane + 32];
        float m = fmaxf(v0, v1);
#pragma unroll
        for (int off = 16; off; off >>= 1) m = fmaxf(m, __shfl_xor_sync(0xffffffffu, m, off));
        float e0 = __expf(v0 - m), e1 = __expf(v1 - m);
        float s = e0 + e1;
#pragma unroll
        for (int off = 16; off; off >>= 1) s += __shfl_xor_sync(0xffffffffu, s, off);
        float inv = 1.0f / s;
        size_t base = (size_t)bh * 4096 + r * 64;
        g_at[base + lane]      = __float2half_rn(e0 * inv * rv_s[lane]);
        g_at[base + lane + 32] = __float2half_rn(e1 * inv * rv_s[lane + 32]);
    }
}

// ---------------- wprime: W'[b][:, h*64:(h+1)*64] = P[:, h*64:..] @ attn_bh ----------------
// grid (2, 64): blockIdx.x = m-half (256 rows), blockIdx.y = bh. 256 threads.
#define WP_P  0
#define WP_A  32768
#define WP_SMEM 40960

__global__ __launch_bounds__(256) void wprime_kernel() {
    extern __shared__ char smem[];
    uint32_t sb = smem_u32(smem);
    int mhalf = blockIdx.x;
    int bh = blockIdx.y;
    int b = bh >> 3, hg = bh & 7;
    int tid = threadIdx.x, l = tid & 31, wid = tid >> 5;
    int wm = wid >> 1, wn = wid & 1;   // 4 warps M (64 rows), 2 warps N (32 cols)

    const __half* Pw = g_wh + 3 * C_ * C_;   // proj weights
#pragma unroll
    for (int it = 0; it < 8; it++) {
        int idx = tid + it * 256;            // 0..2047
        int r = idx >> 3;                    // 0..255
        int c8 = idx & 7;
        uint32_t swo = sw128((uint32_t)(r * 128 + c8 * 16));
        CP16(sb + WP_P + swo, Pw + (size_t)(mhalf * 256 + r) * C_ + hg * 64 + c8 * 8);
    }
#pragma unroll
    for (int it = 0; it < 2; it++) {
        int idx = tid + it * 256;            // 0..511
        int r = idx >> 3;                    // 0..63
        int c8 = idx & 7;
        uint32_t swo = sw128((uint32_t)(r * 128 + c8 * 16));
        CP16(sb + WP_A + swo, g_at + (size_t)bh * 4096 + r * 64 + c8 * 8);
    }
    CP_COMMIT();
    CP_WAIT0();
    __syncthreads();

    float acc[4][4][4] = {};
    int lr = l & 15, lc = (l >> 4) << 4;
#pragma unroll
    for (int k16 = 0; k16 < 4; k16++) {
        uint32_t ah[4][4], bf[2][4];
#pragma unroll
        for (int mt = 0; mt < 4; mt++) {
            uint32_t swo = sw128((uint32_t)((wm * 64 + mt * 16 + lr) * 128 + k16 * 32 + lc));
            LDSM_X4(ah[mt], sb + WP_P + swo);
        }
#pragma unroll
        for (int h = 0; h < 2; h++) {
            uint32_t swo = sw128((uint32_t)((k16 * 16 + lr) * 128 + wn * 64 + h * 32 + lc));
            LDSM_X4T(bf[h], sb + WP_A + swo);
        }
#pragma unroll
        for (int mt = 0; mt < 4; mt++)
#pragma unroll
            for (int nt = 0; nt < 4; nt++) {
                int h = nt >> 1, pr = (nt & 1) * 2;
                MMA16816(acc[mt][nt], ah[mt], bf[h][pr], bf[h][pr + 1]);
            }
    }

    int l4 = l >> 2, l2 = (l & 3) << 1;
#pragma unroll
    for (int mt = 0; mt < 4; mt++)
#pragma unroll
        for (int half = 0; half < 2; half++) {
            int row = mhalf * 256 + wm * 64 + mt * 16 + l4 + half * 8;
            __half* wp = g_wp + ((size_t)b * C_ + row) * C_ + hg * 64;
#pragma unroll
            for (int nt = 0; nt < 4; nt++) {
                int col = wn * 32 + nt * 8 + l2;
                *(uint32_t*)(wp + col) =
                    pack2h(__float2half_rn(acc[mt][nt][half * 2]),
                           __float2half_rn(acc[mt][nt][half * 2 + 1]));
            }
        }
}

// ---------------- launch ----------------
extern "C" void kernel_launch(void* const* d_in, const int* in_sizes, int n_in,
                              void* d_out, int out_size) {
    const float* x  = (const float*)d_in[0];
    const float* dw = (const float*)d_in[1];
    const float* qw = (const float*)d_in[2];
    const float* kw = (const float*)d_in[3];
    const float* vw = (const float*)d_in[4];
    const float* pw = (const float*)d_in[5];
    float* out = (float*)d_out;

    __half *yp, *vp, *whp, *wpp;
    cudaGetSymbolAddress((void**)&yp,  g_y);
    cudaGetSymbolAddress((void**)&vp,  g_v);
    cudaGetSymbolAddress((void**)&whp, g_wh);
    cudaGetSymbolAddress((void**)&wpp, g_wp);

    cudaFuncSetAttribute((const void*)gemm1_kernel<0, 0>, cudaFuncAttributeMaxDynamicSharedMemorySize, Q_SMEM);
    cudaFuncSetAttribute((const void*)gemm1_kernel<1, 1>, cudaFuncAttributeMaxDynamicSharedMemorySize, Q_SMEM);
    cudaFuncSetAttribute((const void*)scores_kernel, cudaFuncAttributeMaxDynamicSharedMemorySize, SC_SMEM);
    cudaFuncSetAttribute((const void*)wprime_kernel, cudaFuncAttributeMaxDynamicSharedMemorySize, WP_SMEM);

    // 1: dwconv + weight convert + zero counters (fused)
    prep_kernel<<<dim3(16, 4096 + 256), 256>>>(x, dw, qw, kw, vw, pw);
    // 2: fused QKV GEMM, M=1536, CTA 128x128
    gemm1_kernel<0, 0><<<dim3(NPIX / 128, 12, B_), 256, Q_SMEM>>>(whp, yp, nullptr);
    // 3: scores + fused softmax
    scores_kernel<<<dim3(NSPLIT, B_ * HEADS_), 256, SC_SMEM>>>();
    // 4: W' = P @ blockdiag(attn)   (replaces apply)
    wprime_kernel<<<dim3(2, B_ * HEADS_), 256, WP_SMEM>>>();
    // 5: out = W'[b] @ v[b]   (proj GEMM, per-batch A)
    gemm1_kernel<1, 1><<<dim3(NPIX / 128, 4, B_), 256, Q_SMEM>>>(wpp, vp, out);
}

// round 16
// speedup vs baseline: 1.6563x; 1.0801x over previous
#include <cuda_runtime.h>
#include <cuda_fp16.h>
#include <math.h>
#include <stdint.h>

#define B_     8
#define C_     512
#define HH     64
#define WW     64
#define NPIX   4096
#define HEADS_ 8
#define HD     64
#define TOFF   (B_ * C_ * NPIX)
#define NSPLIT 16

// ---------------- scratch ----------------
__device__ __align__(16) __half g_y [TOFF];
__device__ __align__(16) __half g_q [TOFF], g_k[TOFF], g_v[TOFF];
__device__ __align__(16) __half g_wh[4 * C_ * C_];
__device__ __align__(16) __half g_wp[B_ * C_ * C_];
__device__ __align__(16) __half g_at[B_ * HEADS_ * HD * HD];
__device__ float g_part[B_ * HEADS_ * NSPLIT * HD * HD];
__device__ float g_sq[3 * B_ * C_];
__device__ int   g_cnt[B_ * HEADS_];

// ---------------- PTX helpers (baseline sm_80+) ----------------
__device__ __forceinline__ uint32_t smem_u32(const void* p) {
    uint32_t a;
    asm("{ .reg .u64 t; cvta.to.shared.u64 t, %1; cvt.u32.u64 %0, t; }" : "=r"(a) : "l"(p));
    return a;
}
#define CP16(s, g) asm volatile("cp.async.cg.shared.global [%0], [%1], 16;" :: "r"(s), "l"(g))
#define CP_COMMIT() asm volatile("cp.async.commit_group;" ::: "memory")
#define CP_WAIT(n)  asm volatile("cp.async.wait_group %0;" :: "n"(n) : "memory")
#define CP_WAIT0()  asm volatile("cp.async.wait_group 0;" ::: "memory")

#define LDSM_X4(r, a) \
    asm volatile("ldmatrix.sync.aligned.m8n8.x4.shared.b16 {%0,%1,%2,%3}, [%4];" \
        : "=r"((r)[0]), "=r"((r)[1]), "=r"((r)[2]), "=r"((r)[3]) : "r"(a))
#define LDSM_X4T(r, a) \
    asm volatile("ldmatrix.sync.aligned.m8n8.x4.trans.shared.b16 {%0,%1,%2,%3}, [%4];" \
        : "=r"((r)[0]), "=r"((r)[1]), "=r"((r)[2]), "=r"((r)[3]) : "r"(a))
#define MMA16816(d, a, b0, b1) \
    asm volatile("mma.sync.aligned.m16n8k16.row.col.f32.f16.f16.f32 " \
        "{%0,%1,%2,%3}, {%4,%5,%6,%7}, {%8,%9}, {%0,%1,%2,%3};" \
        : "+f"((d)[0]), "+f"((d)[1]), "+f"((d)[2]), "+f"((d)[3]) \
        : "r"((a)[0]), "r"((a)[1]), "r"((a)[2]), "r"((a)[3]), "r"(b0), "r"(b1))

__device__ __forceinline__ uint32_t sw128(uint32_t o) { return o ^ ((o >> 3) & 0x70); }

__device__ __forceinline__ uint32_t pack2h(__half a, __half b) {
    unsigned short ua = *(unsigned short*)&a, ub = *(unsigned short*)&b;
    return (uint32_t)ua | ((uint32_t)ub << 16);
}
__device__ __forceinline__ float inv_norm(float s) {
    return 1.0f / fmaxf(sqrtf(s), 1e-12f);
}

// ---------------- fused prep: dwconv (1 CTA/plane) | weight convert + zero ----------------
__global__ __launch_bounds__(256) void prep_kernel(const float* __restrict__ x,
                                                   const float* __restrict__ w,
                                                   const float* __restrict__ qw,
                                                   const float* __restrict__ kw,
                                                   const float* __restrict__ vw,
                                                   const float* __restrict__ pw) {
    int by = blockIdx.x;
    if (by < 4096) {
        // ---- dwconv: one CTA per (b,c) plane, 16 px per thread ----
        int plane = by;
        int c = plane & (C_ - 1);
        __shared__ float ws[9];
        if (threadIdx.x < 9) ws[threadIdx.x] = w[c * 9 + threadIdx.x];
        __syncthreads();
        const float* xp = x + (size_t)plane * NPIX;
        __half* yp = g_y + (size_t)plane * NPIX;
        int tid = threadIdx.x;
#pragma unroll
        for (int i = 0; i < 16; i++) {
            int p = tid + i * 256;
            int h = p >> 6, wc = p & 63;
            float acc = 0.f;
#pragma unroll
            for (int kh = 0; kh < 3; kh++) {
                int hh = h + kh - 1;
                if (hh < 0 || hh >= HH) continue;
#pragma unroll
                for (int kw2 = 0; kw2 < 3; kw2++) {
                    int wcol = wc + kw2 - 1;
                    if (wcol < 0 || wcol >= WW) continue;
                    acc = fmaf(ws[kh * 3 + kw2], xp[hh * WW + wcol], acc);
                }
            }
            yp[p] = __float2half_rn(acc);
        }
    } else {
        // ---- weight convert + zero (g_sq = 12288 floats = 48 blocks of 256) ----
        int cb = by - 4096;                      // 0..4095
        int idx = cb * 256 + threadIdx.x;
        if (cb < 48) {
            g_sq[cb * 256 + threadIdx.x] = 0.f;  // exactly covers 3*B_*C_ = 12288
        }
        if (cb == 48 && threadIdx.x < B_ * HEADS_) g_cnt[threadIdx.x] = 0;
        int m = idx >> 18;
        const float* src = (m == 0) ? qw : (m == 1) ? kw : (m == 2) ? vw : pw;
        g_wh[idx] = __float2half_rn(src[idx & 262143]);
    }
}

// ---------------- QKV GEMM: 1-term fp16, CTA 128x128, 256 threads, 3-stage ----------------
#define Q_A 0
#define Q_B 16384
#define Q_STAGE 32768
#define Q_SMEM (3 * Q_STAGE)

__global__ __launch_bounds__(256, 2) void gemm_qkv_kernel(const __half* __restrict__ Wh,
                                                          const __half* __restrict__ Bg) {
    extern __shared__ char smem[];
    uint32_t sb = smem_u32(smem);
    int tid = threadIdx.x;
    int l = tid & 31, wid = tid >> 5;
    int wm = wid & 3, wn = wid >> 2;        // warp tile: 32 rows x 64 cols
    int bn = blockIdx.x * 128;
    int bm = blockIdx.y * 128;
    int bz = blockIdx.z;
    const __half* Bp = Bg + (size_t)bz * C_ * NPIX;

    auto load_chunk = [&](int chunk, int stg) {
        uint32_t st = sb + stg * Q_STAGE;
        int k0 = chunk * 64;
#pragma unroll
        for (int it = 0; it < 4; it++) {
            int idx = tid + it * 256;
            int ar = idx >> 3;
            int ac = (idx & 7) << 3;
            uint32_t aswo = sw128((uint32_t)(ar * 128 + ac * 2));
            CP16(st + Q_A + aswo, Wh + (size_t)(bm + ar) * C_ + k0 + ac);
            int brr = idx >> 4;
            int bnn = (idx & 15) << 3;
            int s = bnn >> 6, nl = bnn & 63;
            uint32_t bswo = (uint32_t)(s * 8192) + sw128((uint32_t)(brr * 128 + nl * 2));
            CP16(st + Q_B + bswo, Bp + (size_t)(k0 + brr) * NPIX + bn + bnn);
        }
    };

    float acc[2][8][4] = {};
    int lr = l & 15;
    int lc = (l >> 4) << 4;

    load_chunk(0, 0); CP_COMMIT();
    load_chunk(1, 1); CP_COMMIT();

    for (int chunk = 0; chunk < 8; chunk++) {
        CP_WAIT(1);
        __syncthreads();
        uint32_t st = sb + (chunk % 3) * Q_STAGE;
#pragma unroll
        for (int k16 = 0; k16 < 4; k16++) {
            uint32_t ah[2][4], bf[4][4];
#pragma unroll
            for (int mt = 0; mt < 2; mt++) {
                uint32_t swo = sw128((uint32_t)((wm * 32 + mt * 16 + lr) * 128 + k16 * 32 + lc));
                LDSM_X4(ah[mt], st + Q_A + swo);
            }
            uint32_t pb = (uint32_t)(wn * 8192);
#pragma unroll
            for (int h = 0; h < 4; h++) {
                uint32_t swo = sw128((uint32_t)((k16 * 16 + lr) * 128 + h * 32 + lc));
                LDSM_X4T(bf[h], st + Q_B + pb + swo);
            }
#pragma unroll
            for (int mt = 0; mt < 2; mt++)
#pragma unroll
                for (int nt = 0; nt < 8; nt++) {
                    int h = nt >> 1, pr = (nt & 1) * 2;
                    MMA16816(acc[mt][nt], ah[mt], bf[h][pr], bf[h][pr + 1]);
                }
        }
        __syncthreads();
        if (chunk + 2 < 8) load_chunk(chunk + 2, (chunk + 2) % 3);
        CP_COMMIT();
    }

    int l4 = l >> 2, l2 = (l & 3) << 1;
#pragma unroll
    for (int mt = 0; mt < 2; mt++) {
#pragma unroll
        for (int half = 0; half < 2; half++) {
            int row = bm + wm * 32 + mt * 16 + l4 + half * 8;
            int which = row >> 9, ml = row & 511;
            __half* pq = ((which == 0) ? g_q : (which == 1) ? g_k : g_v)
                         + ((size_t)bz * C_ + ml) * NPIX;
            float ss = 0.f;
#pragma unroll
            for (int nt = 0; nt < 8; nt++) {
                int col = bn + wn * 64 + nt * 8 + l2;
                float v0 = acc[mt][nt][half * 2], v1 = acc[mt][nt][half * 2 + 1];
                ss += v0 * v0 + v1 * v1;
                *(uint32_t*)(pq + col) = pack2h(__float2half_rn(v0), __float2half_rn(v1));
            }
            ss += __shfl_xor_sync(0xffffffffu, ss, 1);
            ss += __shfl_xor_sync(0xffffffffu, ss, 2);
            if ((l & 3) == 0)
                atomicAdd(&g_sq[which * (B_ * C_) + bz * C_ + ml], ss);
        }
    }
}

// ---------------- proj GEMM: 1-term fp16, CTA 64x128, 4-stage, per-batch A ----------------
#define P_A 0
#define P_B 8192
#define P_STAGE 24576
#define P_SMEM (4 * P_STAGE)

__global__ __launch_bounds__(256, 2) void gemm_proj_kernel(const __half* __restrict__ Wg,
                                                           const __half* __restrict__ Bg,
                                                           float* __restrict__ Cout) {
    extern __shared__ char smem[];
    uint32_t sb = smem_u32(smem);
    int tid = threadIdx.x;
    int l = tid & 31, wid = tid >> 5;
    int wm = wid & 1, wn = wid >> 1;        // warp tile: 32 rows x 32 cols
    int bn = blockIdx.x * 128;
    int bm = blockIdx.y * 64;
    int bz = blockIdx.z;
    const __half* Ap = Wg + (size_t)bz * C_ * C_;
    const __half* Bp = Bg + (size_t)bz * C_ * NPIX;

    auto load_chunk = [&](int chunk, int stg) {
        uint32_t st = sb + stg * P_STAGE;
        int k0 = chunk * 64;
#pragma unroll
        for (int it = 0; it < 2; it++) {
            int idx = tid + it * 256;
            int ar = idx >> 3;
            int ac = (idx & 7) << 3;
            uint32_t aswo = sw128((uint32_t)(ar * 128 + ac * 2));
            CP16(st + P_A + aswo, Ap + (size_t)(bm + ar) * C_ + k0 + ac);
        }
#pragma unroll
        for (int it = 0; it < 4; it++) {
            int idx = tid + it * 256;
            int brr = idx >> 4;
            int bnn = (idx & 15) << 3;
            int s = bnn >> 6, nl = bnn & 63;
            uint32_t bswo = (uint32_t)(s * 8192) + sw128((uint32_t)(brr * 128 + nl * 2));
            CP16(st + P_B + bswo, Bp + (size_t)(k0 + brr) * NPIX + bn + bnn);
        }
    };

    float acc[2][4][4] = {};
    int lr = l & 15;
    int lc = (l >> 4) << 4;

    load_chunk(0, 0); CP_COMMIT();
    load_chunk(1, 1); CP_COMMIT();
    load_chunk(2, 2); CP_COMMIT();

    for (int chunk = 0; chunk < 8; chunk++) {
        CP_WAIT(2);
        __syncthreads();
        uint32_t st = sb + (chunk & 3) * P_STAGE;
#pragma unroll
        for (int k16 = 0; k16 < 4; k16++) {
            uint32_t ah[2][4], bf[2][4];
            int kb = k16 * 32 + lc;
#pragma unroll
            for (int mt = 0; mt < 2; mt++) {
                uint32_t swo = sw128((uint32_t)((wm * 32 + mt * 16 + lr) * 128 + kb));
                LDSM_X4(ah[mt], st + P_A + swo);
            }
            uint32_t pb = (uint32_t)((wn >> 1) * 8192);
#pragma unroll
            for (int h = 0; h < 2; h++) {
                uint32_t swo = sw128((uint32_t)((k16 * 16 + lr) * 128 + (wn & 1) * 64 + h * 32 + lc));
                LDSM_X4T(bf[h], st + P_B + pb + swo);
            }
#pragma unroll
            for (int mt = 0; mt < 2; mt++)
#pragma unroll
                for (int nt = 0; nt < 4; nt++) {
                    int h = nt >> 1, pr = (nt & 1) * 2;
                    MMA16816(acc[mt][nt], ah[mt], bf[h][pr], bf[h][pr + 1]);
                }
        }
        __syncthreads();
        if (chunk + 3 < 8) load_chunk(chunk + 3, (chunk + 3) & 3);
        CP_COMMIT();
    }

    int l4 = l >> 2, l2 = (l & 3) << 1;
#pragma unroll
    for (int mt = 0; mt < 2; mt++)
#pragma unroll
        for (int half = 0; half < 2; half++) {
            int row = bm + wm * 32 + mt * 16 + l4 + half * 8;
            float* base = Cout + ((size_t)bz * C_ + row) * NPIX;
#pragma unroll
            for (int nt = 0; nt < 4; nt++) {
                int col = bn + wn * 32 + nt * 8 + l2;
                *(float2*)(base + col) =
                    make_float2(acc[mt][nt][half * 2], acc[mt][nt][half * 2 + 1]);
            }
        }
}

// ---------------- scores + fused softmax (threadfence reduction) ----------------
#define SC_Q 0
#define SC_K 8192
#define SC_STAGE 16384
#define SC_SMEM (2 * SC_STAGE)

__global__ __launch_bounds__(256) void scores_kernel() {
    extern __shared__ char smem[];
    uint32_t sb = smem_u32(smem);
    int sp = blockIdx.x, bh = blockIdx.y;
    int b = bh >> 3, hg = bh & 7;
    int tid = threadIdx.x, l = tid & 31, wid = tid >> 5;
    int wm = wid & 1, wn = wid >> 1;
    const __half* qp = g_q + ((size_t)b * C_ + hg * HD) * NPIX;
    const __half* kp = g_k + ((size_t)b * C_ + hg * HD) * NPIX;
    int px0 = sp * 256;

    auto load_chunk = [&](int chunk, int stg) {
        uint32_t st = sb + stg * SC_STAGE;
        int k0 = px0 + chunk * 64;
#pragma unroll
        for (int it = 0; it < 2; it++) {
            int idx = tid + it * 256;
            int r = idx >> 3;
            int c8 = idx & 7;
            uint32_t swo = sw128((uint32_t)(r * 128 + c8 * 16));
            size_t go = (size_t)r * NPIX + k0 + c8 * 8;
            CP16(st + SC_Q + swo, qp + go);
            CP16(st + SC_K + swo, kp + go);
        }
    };

    float acc[2][2][4] = {};
    int lr = l & 15, lc = (l >> 4) << 4;
    int bn_row = wn * 16 + (l & 7) + ((l >> 4) << 3);
    int bn_kb = ((l >> 3) & 1) * 16;

    load_chunk(0, 0); CP_COMMIT();
    load_chunk(1, 1); CP_COMMIT();

    for (int chunk = 0; chunk < 4; chunk++) {
        CP_WAIT(1);
        __syncthreads();
        uint32_t st = sb + (chunk & 1) * SC_STAGE;
#pragma unroll
        for (int k16 = 0; k16 < 4; k16++) {
            uint32_t ah[2][4], bf[4];
#pragma unroll
            for (int mt = 0; mt < 2; mt++) {
                uint32_t swo = sw128((uint32_t)((wm * 32 + mt * 16 + lr) * 128 + k16 * 32 + lc));
                LDSM_X4(ah[mt], st + SC_Q + swo);
            }
            uint32_t swb = sw128((uint32_t)(bn_row * 128 + k16 * 32 + bn_kb));
            LDSM_X4(bf, st + SC_K + swb);
#pragma unroll
            for (int mt = 0; mt < 2; mt++)
#pragma unroll
                for (int nt = 0; nt < 2; nt++)
                    MMA16816(acc[mt][nt], ah[mt], bf[nt * 2], bf[nt * 2 + 1]);
        }
        __syncthreads();
        if (chunk + 2 < 4) load_chunk(chunk + 2, chunk & 1);
        CP_COMMIT();
    }

    float* op = g_part + ((size_t)bh * NSPLIT + sp) * 4096;
    int l4 = l >> 2, l2 = (l & 3) << 1;
#pragma unroll
    for (int mt = 0; mt < 2; mt++)
#pragma unroll
        for (int half = 0; half < 2; half++) {
            int row = wm * 32 + mt * 16 + l4 + half * 8;
#pragma unroll
            for (int nt = 0; nt < 2; nt++) {
                int col = wn * 16 + nt * 8 + l2;
                *(float2*)(op + row * 64 + col) =
                    make_float2(acc[mt][nt][half * 2], acc[mt][nt][half * 2 + 1]);
            }
        }

    __syncthreads();
    __threadfence();
    __shared__ int is_last;
    if (tid == 0) {
        int old = atomicAdd(&g_cnt[bh], 1);
        is_last = (old == NSPLIT - 1) ? 1 : 0;
        if (is_last) g_cnt[bh] = 0;   // self-reset for graph replay safety
    }
    __syncthreads();
    if (!is_last) return;
    __threadfence();

    float* Ss = (float*)smem;
    float* rv_s = (float*)(smem + 16384);
    int cb = b * C_ + hg * HD;
    const float scale = 0.125f;
    if (tid < 64) rv_s[tid] = inv_norm(g_sq[2 * B_ * C_ + cb + tid]);
    for (int i = tid; i < 4096; i += 256) {
        float s = 0.f;
#pragma unroll
        for (int p = 0; p < NSPLIT; p++) s += g_part[((size_t)bh * NSPLIT + p) * 4096 + i];
        int r = i >> 6, c = i & 63;
        Ss[r * 64 + c] = s * inv_norm(g_sq[cb + r]) * scale * inv_norm(g_sq[B_ * C_ + cb + c]);
    }
    __syncthreads();
    int warp = tid >> 5, lane = tid & 31;
#pragma unroll
    for (int rr = 0; rr < 8; rr++) {
        int r = warp * 8 + rr;
        float v0 = Ss[r * 64 + lane], v1 = Ss[r * 64 + lane + 32];
        float m = fmaxf(v0, v1);
#pragma unroll
        for (int off = 16; off; off >>= 1) m = fmaxf(m, __shfl_xor_sync(0xffffffffu, m, off));
        float e0 = __expf(v0 - m), e1 = __expf(v1 - m);
        float s = e0 + e1;
#pragma unroll
        for (int off = 16; off; off >>= 1) s += __shfl_xor_sync(0xffffffffu, s, off);
        float inv = 1.0f / s;
        size_t base = (size_t)bh * 4096 + r * 64;
        g_at[base + lane]      = __float2half_rn(e0 * inv * rv_s[lane]);
        g_at[base + lane + 32] = __float2half_rn(e1 * inv * rv_s[lane + 32]);
    }
}

// ---------------- wprime: W'[b][:, h*64:(h+1)*64] = P[:, h*64:..] @ attn_bh ----------------
#define WP_P  0
#define WP_A  32768
#define WP_SMEM 40960

__global__ __launch_bounds__(256) void wprime_kernel() {
    extern __shared__ char smem[];
    uint32_t sb = smem_u32(smem);
    int mhalf = blockIdx.x;
    int bh = blockIdx.y;
    int b = bh >> 3, hg = bh & 7;
    int tid = threadIdx.x, l = tid & 31, wid = tid >> 5;
    int wm = wid >> 1, wn = wid & 1;

    const __half* Pw = g_wh + 3 * C_ * C_;
#pragma unroll
    for (int it = 0; it < 8; it++) {
        int idx = tid + it * 256;
        int r = idx >> 3;
        int c8 = idx & 7;
        uint32_t swo = sw128((uint32_t)(r * 128 + c8 * 16));
        CP16(sb + WP_P + swo, Pw + (size_t)(mhalf * 256 + r) * C_ + hg * 64 + c8 * 8);
    }
#pragma unroll
    for (int it = 0; it < 2; it++) {
        int idx = tid + it * 256;
        int r = idx >> 3;
        int c8 = idx & 7;
        uint32_t swo = sw128((uint32_t)(r * 128 + c8 * 16));
        CP16(sb + WP_A + swo, g_at + (size_t)bh * 4096 + r * 64 + c8 * 8);
    }
    CP_COMMIT();
    CP_WAIT0();
    __syncthreads();

    float acc[4][4][4] = {};
    int lr = l & 15, lc = (l >> 4) << 4;
#pragma unroll
    for (int k16 = 0; k16 < 4; k16++) {
        uint32_t ah[4][4], bf[2][4];
#pragma unroll
        for (int mt = 0; mt < 4; mt++) {
            uint32_t swo = sw128((uint32_t)((wm * 64 + mt * 16 + lr) * 128 + k16 * 32 + lc));
            LDSM_X4(ah[mt], sb + WP_P + swo);
        }
#pragma unroll
        for (int h = 0; h < 2; h++) {
            uint32_t swo = sw128((uint32_t)((k16 * 16 + lr) * 128 + wn * 64 + h * 32 + lc));
            LDSM_X4T(bf[h], sb + WP_A + swo);
        }
#pragma unroll
        for (int mt = 0; mt < 4; mt++)
#pragma unroll
            for (int nt = 0; nt < 4; nt++) {
                int h = nt >> 1, pr = (nt & 1) * 2;
                MMA16816(acc[mt][nt], ah[mt], bf[h][pr], bf[h][pr + 1]);
            }
    }

    int l4 = l >> 2, l2 = (l & 3) << 1;
#pragma unroll
    for (int mt = 0; mt < 4; mt++)
#pragma unroll
        for (int half = 0; half < 2; half++) {
            int row = mhalf * 256 + wm * 64 + mt * 16 + l4 + half * 8;
            __half* wp = g_wp + ((size_t)b * C_ + row) * C_ + hg * 64;
#pragma unroll
            for (int nt = 0; nt < 4; nt++) {
                int col = wn * 32 + nt * 8 + l2;
                *(uint32_t*)(wp + col) =
                    pack2h(__float2half_rn(acc[mt][nt][half * 2]),
                           __float2half_rn(acc[mt][nt][half * 2 + 1]));
            }
        }
}

// ---------------- launch ----------------
extern "C" void kernel_launch(void* const* d_in, const int* in_sizes, int n_in,
                              void* d_out, int out_size) {
    const float* x  = (const float*)d_in[0];
    const float* dw = (const float*)d_in[1];
    const float* qw = (const float*)d_in[2];
    const float* kw = (const float*)d_in[3];
    const float* vw = (const float*)d_in[4];
    const float* pw = (const float*)d_in[5];
    float* out = (float*)d_out;

    __half *yp, *vp, *whp, *wpp;
    cudaGetSymbolAddress((void**)&yp,  g_y);
    cudaGetSymbolAddress((void**)&vp,  g_v);
    cudaGetSymbolAddress((void**)&whp, g_wh);
    cudaGetSymbolAddress((void**)&wpp, g_wp);

    cudaFuncSetAttribute((const void*)gemm_qkv_kernel, cudaFuncAttributeMaxDynamicSharedMemorySize, Q_SMEM);
    cudaFuncSetAttribute((const void*)gemm_proj_kernel, cudaFuncAttributeMaxDynamicSharedMemorySize, P_SMEM);
    cudaFuncSetAttribute((const void*)scores_kernel, cudaFuncAttributeMaxDynamicSharedMemorySize, SC_SMEM);
    cudaFuncSetAttribute((const void*)wprime_kernel, cudaFuncAttributeMaxDynamicSharedMemorySize, WP_SMEM);

    // 1: dwconv (1 CTA/plane) + weight convert + zero g_sq/g_cnt (fused)
    prep_kernel<<<4096 + 4096, 256>>>(x, dw, qw, kw, vw, pw);
    // 2: fused QKV GEMM, M=1536, CTA 128x128
    gemm_qkv_kernel<<<dim3(NPIX / 128, 12, B_), 256, Q_SMEM>>>(whp, yp);
    // 3: scores + fused softmax
    scores_kernel<<<dim3(NSPLIT, B_ * HEADS_), 256, SC_SMEM>>>();
    // 4: W' = P @ blockdiag(attn)
    wprime_kernel<<<dim3(2, B_ * HEADS_), 256, WP_SMEM>>>();
    // 5: out = W'[b] @ v[b]  (M-tile 64, 2048 CTAs for tail fill)
    gemm_proj_kernel<<<dim3(NPIX / 128, 8, B_), 256, P_SMEM>>>(wpp, vp, out);
}

// round 17
// speedup vs baseline: 2.1347x; 1.2888x over previous
#include <cuda_runtime.h>
#include <cuda_fp16.h>
#include <math.h>
#include <stdint.h>

#define B_     8
#define C_     512
#define HH     64
#define WW     64
#define NPIX   4096
#define HEADS_ 8
#define HD     64
#define TOFF   (B_ * C_ * NPIX)
#define GSZ    (C_ * C_)          // 262144 elements per batch Gram

// ---------------- scratch ----------------
__device__ __align__(16) __half g_y [TOFF];
__device__ __align__(16) __half g_wh[4 * C_ * C_];
__device__ __align__(16) float  g_Gp[16 * GSZ];          // split-K=2 Gram partials
__device__ __align__(16) __half g_Ghi[B_ * GSZ], g_Glo[B_ * GSZ];
__device__ __align__(16) __half g_T [B_ * 3 * C_ * C_];  // [b][1536][512]
__device__ __align__(16) __half g_at[B_ * HEADS_ * HD * HD];
__device__ __align__(16) __half g_wp [B_ * C_ * C_];     // W'  = P blockdiag(A)
__device__ __align__(16) __half g_wpp[B_ * C_ * C_];     // W'' = W' Wv
__device__ float g_sq[3 * B_ * C_];

// ---------------- PTX helpers (baseline sm_80+) ----------------
__device__ __forceinline__ uint32_t smem_u32(const void* p) {
    uint32_t a;
    asm("{ .reg .u64 t; cvta.to.shared.u64 t, %1; cvt.u32.u64 %0, t; }" : "=r"(a) : "l"(p));
    return a;
}
#define CP16(s, g) asm volatile("cp.async.cg.shared.global [%0], [%1], 16;" :: "r"(s), "l"(g))
#define CP_COMMIT() asm volatile("cp.async.commit_group;" ::: "memory")
#define CP_WAIT(n)  asm volatile("cp.async.wait_group %0;" :: "n"(n) : "memory")
#define CP_WAIT0()  asm volatile("cp.async.wait_group 0;" ::: "memory")

#define LDSM_X4(r, a) \
    asm volatile("ldmatrix.sync.aligned.m8n8.x4.shared.b16 {%0,%1,%2,%3}, [%4];" \
        : "=r"((r)[0]), "=r"((r)[1]), "=r"((r)[2]), "=r"((r)[3]) : "r"(a))
#define LDSM_X4T(r, a) \
    asm volatile("ldmatrix.sync.aligned.m8n8.x4.trans.shared.b16 {%0,%1,%2,%3}, [%4];" \
        : "=r"((r)[0]), "=r"((r)[1]), "=r"((r)[2]), "=r"((r)[3]) : "r"(a))
#define MMA16816(d, a, b0, b1) \
    asm volatile("mma.sync.aligned.m16n8k16.row.col.f32.f16.f16.f32 " \
        "{%0,%1,%2,%3}, {%4,%5,%6,%7}, {%8,%9}, {%0,%1,%2,%3};" \
        : "+f"((d)[0]), "+f"((d)[1]), "+f"((d)[2]), "+f"((d)[3]) \
        : "r"((a)[0]), "r"((a)[1]), "r"((a)[2]), "r"((a)[3]), "r"(b0), "r"(b1))

__device__ __forceinline__ uint32_t sw128(uint32_t o) { return o ^ ((o >> 3) & 0x70); }

__device__ __forceinline__ uint32_t pack2h(__half a, __half b) {
    unsigned short ua = *(unsigned short*)&a, ub = *(unsigned short*)&b;
    return (uint32_t)ua | ((uint32_t)ub << 16);
}
__device__ __forceinline__ float inv_norm(float s) {
    return 1.0f / fmaxf(sqrtf(s), 1e-12f);
}

// ---------------- prep: dwconv (1 CTA/plane) | weight convert + zero g_sq ----------------
__global__ __launch_bounds__(256) void prep_kernel(const float* __restrict__ x,
                                                   const float* __restrict__ w,
                                                   const float* __restrict__ qw,
                                                   const float* __restrict__ kw,
                                                   const float* __restrict__ vw,
                                                   const float* __restrict__ pw) {
    int by = blockIdx.x;
    if (by < 4096) {
        int plane = by;
        int c = plane & (C_ - 1);
        __shared__ float ws[9];
        if (threadIdx.x < 9) ws[threadIdx.x] = w[c * 9 + threadIdx.x];
        __syncthreads();
        const float* xp = x + (size_t)plane * NPIX;
        __half* yp = g_y + (size_t)plane * NPIX;
        int tid = threadIdx.x;
#pragma unroll
        for (int i = 0; i < 16; i++) {
            int p = tid + i * 256;
            int h = p >> 6, wc = p & 63;
            float acc = 0.f;
#pragma unroll
            for (int kh = 0; kh < 3; kh++) {
                int hh = h + kh - 1;
                if (hh < 0 || hh >= HH) continue;
#pragma unroll
                for (int kw2 = 0; kw2 < 3; kw2++) {
                    int wcol = wc + kw2 - 1;
                    if (wcol < 0 || wcol >= WW) continue;
                    acc = fmaf(ws[kh * 3 + kw2], xp[hh * WW + wcol], acc);
                }
            }
            yp[p] = __float2half_rn(acc);
        }
    } else {
        int cb = by - 4096;
        int idx = cb * 256 + threadIdx.x;
        if (cb < 48) g_sq[cb * 256 + threadIdx.x] = 0.f;  // 48*256 = 12288 = 3*B_*C_
        int m = idx >> 18;
        const float* src = (m == 0) ? qw : (m == 1) ? kw : (m == 2) ? vw : pw;
        g_wh[idx] = __float2half_rn(src[idx & 262143]);
    }
}

// ---------------- Gram: G[b] = Y Yᵀ, split-K 2, fp32 partials ----------------
#define GR_A 0
#define GR_B 16384
#define GR_STAGE 32768
#define GR_SMEM (3 * GR_STAGE)

__global__ __launch_bounds__(256, 2) void gram_kernel() {
    extern __shared__ char smem[];
    uint32_t sb = smem_u32(smem);
    int tid = threadIdx.x, l = tid & 31, wid = tid >> 5;
    int wm = wid & 3, wn = wid >> 2;        // warp tile 32 x 64
    int bn = blockIdx.x * 128;
    int bm = blockIdx.y * 128;
    int bz = blockIdx.z;                    // b*2 + kc
    int b = bz >> 1, kc = bz & 1;
    const __half* Y = g_y + (size_t)b * C_ * NPIX;

    auto load_chunk = [&](int chunk, int stg) {
        uint32_t st = sb + stg * GR_STAGE;
        int k0 = kc * 2048 + chunk * 64;
#pragma unroll
        for (int it = 0; it < 4; it++) {
            int idx = tid + it * 256;              // 0..1023
            int r = idx >> 3;                      // 0..127
            int kcol = (idx & 7) << 3;
            uint32_t swo = sw128((uint32_t)(r * 128 + kcol * 2));
            CP16(st + GR_A + swo, Y + (size_t)(bm + r) * NPIX + k0 + kcol);
            CP16(st + GR_B + swo, Y + (size_t)(bn + r) * NPIX + k0 + kcol);
        }
    };

    float acc[2][8][4] = {};
    int lr = l & 15;
    int lc = (l >> 4) << 4;
    int brow_l = (l & 7) + ((l >> 4) << 3);
    int bkb_l = ((l >> 3) & 1) * 16;

    load_chunk(0, 0); CP_COMMIT();
    load_chunk(1, 1); CP_COMMIT();

    for (int chunk = 0; chunk < 32; chunk++) {
        CP_WAIT(1);
        __syncthreads();
        uint32_t st = sb + (chunk % 3) * GR_STAGE;
#pragma unroll
        for (int k16 = 0; k16 < 4; k16++) {
            uint32_t ah[2][4], bg[4][4];
#pragma unroll
            for (int mt = 0; mt < 2; mt++) {
                uint32_t swo = sw128((uint32_t)((wm * 32 + mt * 16 + lr) * 128 + k16 * 32 + lc));
                LDSM_X4(ah[mt], st + GR_A + swo);
            }
#pragma unroll
            for (int g = 0; g < 4; g++) {
                int brow = wn * 64 + g * 16 + brow_l;
                uint32_t swo = sw128((uint32_t)(brow * 128 + k16 * 32 + bkb_l));
                LDSM_X4(bg[g], st + GR_B + swo);
            }
#pragma unroll
            for (int mt = 0; mt < 2; mt++)
#pragma unroll
                for (int g = 0; g < 4; g++)
#pragma unroll
                    for (int j = 0; j < 2; j++)
                        MMA16816(acc[mt][g * 2 + j], ah[mt], bg[g][j * 2], bg[g][j * 2 + 1]);
        }
        __syncthreads();
        if (chunk + 2 < 32) load_chunk(chunk + 2, (chunk + 2) % 3);
        CP_COMMIT();
    }

    float* gp = g_Gp + (size_t)bz * GSZ;
    int l4 = l >> 2, l2 = (l & 3) << 1;
#pragma unroll
    for (int mt = 0; mt < 2; mt++)
#pragma unroll
        for (int half = 0; half < 2; half++) {
            int row = bm + wm * 32 + mt * 16 + l4 + half * 8;
#pragma unroll
            for (int nt = 0; nt < 8; nt++) {
                int col = bn + wn * 64 + nt * 8 + l2;
                *(float2*)&gp[(size_t)row * 512 + col] =
                    make_float2(acc[mt][nt][half * 2], acc[mt][nt][half * 2 + 1]);
            }
        }
}

// ---------------- gcvt: sum split-K partials, split to hi/lo fp16 ----------------
__global__ __launch_bounds__(256) void gcvt_kernel() {
    size_t gi = ((size_t)blockIdx.x * 256 + threadIdx.x) * 4;   // over 8*GSZ elements
    int b = (int)(gi >> 18);
    size_t e = gi & (GSZ - 1);
    const float4 fa = *(const float4*)&g_Gp[((size_t)(2 * b) << 18) + e];
    const float4 fb = *(const float4*)&g_Gp[((size_t)(2 * b + 1) << 18) + e];
    float s[4] = {fa.x + fb.x, fa.y + fb.y, fa.z + fb.z, fa.w + fb.w};
    __half hi[4], lo[4];
#pragma unroll
    for (int i = 0; i < 4; i++) {
        hi[i] = __float2half_rn(s[i]);
        lo[i] = __float2half_rn(s[i] - __half2float(hi[i]));
    }
    size_t o = ((size_t)b << 18) + e;
    *(uint2*)&g_Ghi[o] = make_uint2(pack2h(hi[0], hi[1]), pack2h(hi[2], hi[3]));
    *(uint2*)&g_Glo[o] = make_uint2(pack2h(lo[0], lo[1]), pack2h(lo[2], lo[3]));
}

// ---------------- T = [Wq;Wk;Wv] @ G (2-term hi/lo), epilogue row-dot norms ----------------
#define T_A   0
#define T_BHI 16384
#define T_BLO 32768
#define T_STAGE 49152
#define T_SMEM (2 * T_STAGE)

__global__ __launch_bounds__(256, 2) void gemmT_kernel() {
    extern __shared__ char smem[];
    uint32_t sb = smem_u32(smem);
    int tid = threadIdx.x, l = tid & 31, wid = tid >> 5;
    int wm = wid & 3, wn = wid >> 2;        // warp tile 32 x 64
    int bn = blockIdx.x * 128;              // grid.x = 4 (N=512)
    int bm = blockIdx.y * 128;              // grid.y = 12 (M=1536)
    int bz = blockIdx.z;
    const __half* Bh = g_Ghi + (size_t)bz * GSZ;
    const __half* Bl = g_Glo + (size_t)bz * GSZ;

    auto load_chunk = [&](int chunk, int stg) {
        uint32_t st = sb + stg * T_STAGE;
        int k0 = chunk * 64;
#pragma unroll
        for (int it = 0; it < 4; it++) {
            int idx = tid + it * 256;              // 0..1023
            int ar = idx >> 3;                     // 0..127
            int ac = (idx & 7) << 3;
            uint32_t aswo = sw128((uint32_t)(ar * 128 + ac * 2));
            CP16(st + T_A + aswo, g_wh + (size_t)(bm + ar) * C_ + k0 + ac);
            int brr = idx >> 4;                    // 0..63
            int bnn = (idx & 15) << 3;
            int s = bnn >> 6, nl = bnn & 63;
            uint32_t bswo = (uint32_t)(s * 8192) + sw128((uint32_t)(brr * 128 + nl * 2));
            CP16(st + T_BHI + bswo, Bh + (size_t)(k0 + brr) * 512 + bn + bnn);
            CP16(st + T_BLO + bswo, Bl + (size_t)(k0 + brr) * 512 + bn + bnn);
        }
    };

    float acc[2][8][4] = {};
    int lr = l & 15;
    int lc = (l >> 4) << 4;

    load_chunk(0, 0); CP_COMMIT();
    load_chunk(1, 1); CP_COMMIT();

    for (int chunk = 0; chunk < 8; chunk++) {
        CP_WAIT(1);
        __syncthreads();
        uint32_t st = sb + (chunk & 1) * T_STAGE;
#pragma unroll
        for (int k16 = 0; k16 < 4; k16++) {
            uint32_t ah[2][4];
#pragma unroll
            for (int mt = 0; mt < 2; mt++) {
                uint32_t swo = sw128((uint32_t)((wm * 32 + mt * 16 + lr) * 128 + k16 * 32 + lc));
                LDSM_X4(ah[mt], st + T_A + swo);
            }
            uint32_t pb = (uint32_t)(wn * 8192);
#pragma unroll
            for (int term = 0; term < 2; term++) {
                uint32_t base = (term == 0) ? (st + T_BHI) : (st + T_BLO);
                uint32_t bf[4][4];
#pragma unroll
                for (int h = 0; h < 4; h++) {
                    uint32_t swo = sw128((uint32_t)((k16 * 16 + lr) * 128 + h * 32 + lc));
                    LDSM_X4T(bf[h], base + pb + swo);
                }
#pragma unroll
                for (int mt = 0; mt < 2; mt++)
#pragma unroll
                    for (int nt = 0; nt < 8; nt++) {
                        int h = nt >> 1, pr = (nt & 1) * 2;
                        MMA16816(acc[mt][nt], ah[mt], bf[h][pr], bf[h][pr + 1]);
                    }
            }
        }
        __syncthreads();
        if (chunk + 2 < 8) load_chunk(chunk + 2, (chunk + 2) & 1);
        CP_COMMIT();
    }

    // epilogue: write T fp16 + accumulate row dots with W for norms
    int l4 = l >> 2, l2 = (l & 3) << 1;
#pragma unroll
    for (int mt = 0; mt < 2; mt++) {
#pragma unroll
        for (int half = 0; half < 2; half++) {
            int row = bm + wm * 32 + mt * 16 + l4 + half * 8;     // 0..1535
            __half* tp = g_T + ((size_t)bz * 1536 + row) * 512;
            float ss = 0.f;
#pragma unroll
            for (int nt = 0; nt < 8; nt++) {
                int col = bn + wn * 64 + nt * 8 + l2;
                float v0 = acc[mt][nt][half * 2], v1 = acc[mt][nt][half * 2 + 1];
                *(uint32_t*)(tp + col) = pack2h(__float2half_rn(v0), __float2half_rn(v1));
                uint32_t wpk = *(const uint32_t*)&g_wh[(size_t)row * C_ + col];
                __half2 wh2 = *(__half2*)&wpk;
                ss += v0 * __half2float(__low2half(wh2)) + v1 * __half2float(__high2half(wh2));
            }
            ss += __shfl_xor_sync(0xffffffffu, ss, 1);
            ss += __shfl_xor_sync(0xffffffffu, ss, 2);
            if ((l & 3) == 0) {
                int which = row >> 9, ml = row & 511;
                atomicAdd(&g_sq[which * (B_ * C_) + bz * C_ + ml], ss);
            }
        }
    }
}

// ---------------- scores + softmax: S_bh = Tq_h @ Wk_hᵀ (64x64xK512) ----------------
#define S2_STAGE 16384
#define S2_SMEM (2 * S2_STAGE)

__global__ __launch_bounds__(256) void scores_kernel() {
    extern __shared__ char smem[];
    uint32_t sb = smem_u32(smem);
    int bh = blockIdx.x;
    int b = bh >> 3, hg = bh & 7;
    int tid = threadIdx.x, l = tid & 31, wid = tid >> 5;
    int wm = wid & 1, wn = wid >> 1;
    const __half* tp = g_T + ((size_t)b * 1536 + hg * 64) * 512;       // Tq rows
    const __half* kw = g_wh + (size_t)(C_ + hg * 64) * C_;             // Wk rows

    auto load_chunk = [&](int chunk, int stg) {
        uint32_t st = sb + stg * S2_STAGE;
        int k0 = chunk * 64;
#pragma unroll
        for (int it = 0; it < 2; it++) {
            int idx = tid + it * 256;
            int r = idx >> 3;
            int c8 = idx & 7;
            uint32_t swo = sw128((uint32_t)(r * 128 + c8 * 16));
            CP16(st + 0 + swo, tp + (size_t)r * 512 + k0 + c8 * 8);
            CP16(st + 8192 + swo, kw + (size_t)r * 512 + k0 + c8 * 8);
        }
    };

    float acc[2][2][4] = {};
    int lr = l & 15, lc = (l >> 4) << 4;
    int bn_row = wn * 16 + (l & 7) + ((l >> 4) << 3);
    int bn_kb = ((l >> 3) & 1) * 16;

    load_chunk(0, 0); CP_COMMIT();
    load_chunk(1, 1); CP_COMMIT();

    for (int chunk = 0; chunk < 8; chunk++) {
        CP_WAIT(1);
        __syncthreads();
        uint32_t st = sb + (chunk & 1) * S2_STAGE;
#pragma unroll
        for (int k16 = 0; k16 < 4; k16++) {
            uint32_t ah[2][4], bf[4];
#pragma unroll
            for (int mt = 0; mt < 2; mt++) {
                uint32_t swo = sw128((uint32_t)((wm * 32 + mt * 16 + lr) * 128 + k16 * 32 + lc));
                LDSM_X4(ah[mt], st + 0 + swo);
            }
            uint32_t swb = sw128((uint32_t)(bn_row * 128 + k16 * 32 + bn_kb));
            LDSM_X4(bf, st + 8192 + swb);
#pragma unroll
            for (int mt = 0; mt < 2; mt++)
#pragma unroll
                for (int nt = 0; nt < 2; nt++)
                    MMA16816(acc[mt][nt], ah[mt], bf[nt * 2], bf[nt * 2 + 1]);
        }
        __syncthreads();
        if (chunk + 2 < 8) load_chunk(chunk + 2, chunk & 1);
        CP_COMMIT();
    }

    // fused softmax: reuse stage smem for the 64x64 score tile
    __shared__ float rqs[64], rks[64], rvs[64];
    int cb = b * C_ + hg * 64;
    if (tid < 64) {
        rqs[tid] = inv_norm(g_sq[cb + tid]) * 0.125f;
        rks[tid] = inv_norm(g_sq[B_ * C_ + cb + tid]);
        rvs[tid] = inv_norm(g_sq[2 * B_ * C_ + cb + tid]);
    }
    __syncthreads();            // stage reads done + rqs/rks ready
    float* Ss = (float*)smem;   // 16 KB overlay
    int l4 = l >> 2, l2 = (l & 3) << 1;
#pragma unroll
    for (int mt = 0; mt < 2; mt++)
#pragma unroll
        for (int half = 0; half < 2; half++) {
            int row = wm * 32 + mt * 16 + l4 + half * 8;
#pragma unroll
            for (int nt = 0; nt < 2; nt++) {
                int col = wn * 16 + nt * 8 + l2;
                Ss[row * 64 + col]     = acc[mt][nt][half * 2] * rqs[row] * rks[col];
                Ss[row * 64 + col + 1] = acc[mt][nt][half * 2 + 1] * rqs[row] * rks[col + 1];
            }
        }
    __syncthreads();
    int warp = tid >> 5, lane = tid & 31;
#pragma unroll
    for (int rr = 0; rr < 8; rr++) {
        int r = warp * 8 + rr;
        float v0 = Ss[r * 64 + lane], v1 = Ss[r * 64 + lane + 32];
        float m = fmaxf(v0, v1);
#pragma unroll
        for (int off = 16; off; off >>= 1) m = fmaxf(m, __shfl_xor_sync(0xffffffffu, m, off));
        float e0 = __expf(v0 - m), e1 = __expf(v1 - m);
        float s = e0 + e1;
#pragma unroll
        for (int off = 16; off; off >>= 1) s += __shfl_xor_sync(0xffffffffu, s, off);
        float inv = 1.0f / s;
        size_t base = (size_t)bh * 4096 + r * 64;
        g_at[base + lane]      = __float2half_rn(e0 * inv * rvs[lane]);
        g_at[base + lane + 32] = __float2half_rn(e1 * inv * rvs[lane + 32]);
    }
}

// ---------------- wprime: W'[b][:, h*64:+64] = P[:, h*64:+64] @ A_bh ----------------
#define WP_P  0
#define WP_A  32768
#define WP_SMEM 40960

__global__ __launch_bounds__(256) void wprime_kernel() {
    extern __shared__ char smem[];
    uint32_t sb = smem_u32(smem);
    int mhalf = blockIdx.x;
    int bh = blockIdx.y;
    int b = bh >> 3, hg = bh & 7;
    int tid = threadIdx.x, l = tid & 31, wid = tid >> 5;
    int wm = wid >> 1, wn = wid & 1;

    const __half* Pw = g_wh + 3 * C_ * C_;
#pragma unroll
    for (int it = 0; it < 8; it++) {
        int idx = tid + it * 256;
        int r = idx >> 3;
        int c8 = idx & 7;
        uint32_t swo = sw128((uint32_t)(r * 128 + c8 * 16));
        CP16(sb + WP_P + swo, Pw + (size_t)(mhalf * 256 + r) * C_ + hg * 64 + c8 * 8);
    }
#pragma unroll
    for (int it = 0; it < 2; it++) {
        int idx = tid + it * 256;
        int r = idx >> 3;
        int c8 = idx & 7;
        uint32_t swo = sw128((uint32_t)(r * 128 + c8 * 16));
        CP16(sb + WP_A + swo, g_at + (size_t)bh * 4096 + r * 64 + c8 * 8);
    }
    CP_COMMIT();
    CP_WAIT0();
    __syncthreads();

    float acc[4][4][4] = {};
    int lr = l & 15, lc = (l >> 4) << 4;
#pragma unroll
    for (int k16 = 0; k16 < 4; k16++) {
        uint32_t ah[4][4], bf[2][4];
#pragma unroll
        for (int mt = 0; mt < 4; mt++) {
            uint32_t swo = sw128((uint32_t)((wm * 64 + mt * 16 + lr) * 128 + k16 * 32 + lc));
            LDSM_X4(ah[mt], sb + WP_P + swo);
        }
#pragma unroll
        for (int h = 0; h < 2; h++) {
            uint32_t swo = sw128((uint32_t)((k16 * 16 + lr) * 128 + wn * 64 + h * 32 + lc));
            LDSM_X4T(bf[h], sb + WP_A + swo);
        }
#pragma unroll
        for (int mt = 0; mt < 4; mt++)
#pragma unroll
            for (int nt = 0; nt < 4; nt++) {
                int h = nt >> 1, pr = (nt & 1) * 2;
                MMA16816(acc[mt][nt], ah[mt], bf[h][pr], bf[h][pr + 1]);
            }
    }

    int l4 = l >> 2, l2 = (l & 3) << 1;
#pragma unroll
    for (int mt = 0; mt < 4; mt++)
#pragma unroll
        for (int half = 0; half < 2; half++) {
            int row = mhalf * 256 + wm * 64 + mt * 16 + l4 + half * 8;
            __half* wp = g_wp + ((size_t)b * C_ + row) * C_ + hg * 64;
#pragma unroll
            for (int nt = 0; nt < 4; nt++) {
                int col = wn * 32 + nt * 8 + l2;
                *(uint32_t*)(wp + col) =
                    pack2h(__float2half_rn(acc[mt][nt][half * 2]),
                           __float2half_rn(acc[mt][nt][half * 2 + 1]));
            }
        }
}

// ---------------- generic 1-term GEMM: CTA 64x128, 4-stage (proj template) ----------------
// C[b] = A[b] (per-batch, row stride C_) @ B (row stride brs, batch stride bbs)
#define P_A 0
#define P_B 8192
#define P_STAGE 24576
#define P_SMEM (4 * P_STAGE)

template <int OUTHALF>
__global__ __launch_bounds__(256, 2) void gemm_ab_kernel(const __half* __restrict__ Wg,
                                                         const __half* __restrict__ Bg,
                                                         void* __restrict__ outp,
                                                         int brs, size_t bbs) {
    extern __shared__ char smem[];
    uint32_t sb = smem_u32(smem);
    int tid = threadIdx.x;
    int l = tid & 31, wid = tid >> 5;
    int wm = wid & 1, wn = wid >> 1;
    int bn = blockIdx.x * 128;
    int bm = blockIdx.y * 64;
    int bz = blockIdx.z;
    const __half* Ap = Wg + (size_t)bz * C_ * C_;
    const __half* Bp = Bg + (size_t)bz * bbs;

    auto load_chunk = [&](int chunk, int stg) {
        uint32_t st = sb + stg * P_STAGE;
        int k0 = chunk * 64;
#pragma unroll
        for (int it = 0; it < 2; it++) {
            int idx = tid + it * 256;
            int ar = idx >> 3;
            int ac = (idx & 7) << 3;
            uint32_t aswo = sw128((uint32_t)(ar * 128 + ac * 2));
            CP16(st + P_A + aswo, Ap + (size_t)(bm + ar) * C_ + k0 + ac);
        }
#pragma unroll
        for (int it = 0; it < 4; it++) {
            int idx = tid + it * 256;
            int brr = idx >> 4;
            int bnn = (idx & 15) << 3;
            int s = bnn >> 6, nl = bnn & 63;
            uint32_t bswo = (uint32_t)(s * 8192) + sw128((uint32_t)(brr * 128 + nl * 2));
            CP16(st + P_B + bswo, Bp + (size_t)(k0 + brr) * brs + bn + bnn);
        }
    };

    float acc[2][4][4] = {};
    int lr = l & 15;
    int lc = (l >> 4) << 4;

    load_chunk(0, 0); CP_COMMIT();
    load_chunk(1, 1); CP_COMMIT();
    load_chunk(2, 2); CP_COMMIT();

    for (int chunk = 0; chunk < 8; chunk++) {
        CP_WAIT(2);
        __syncthreads();
        uint32_t st = sb + (chunk & 3) * P_STAGE;
#pragma unroll
        for (int k16 = 0; k16 < 4; k16++) {
            uint32_t ah[2][4], bf[2][4];
            int kb = k16 * 32 + lc;
#pragma unroll
            for (int mt = 0; mt < 2; mt++) {
                uint32_t swo = sw128((uint32_t)((wm * 32 + mt * 16 + lr) * 128 + kb));
                LDSM_X4(ah[mt], st + P_A + swo);
            }
            uint32_t pb = (uint32_t)((wn >> 1) * 8192);
#pragma unroll
            for (int h = 0; h < 2; h++) {
                uint32_t swo = sw128((uint32_t)((k16 * 16 + lr) * 128 + (wn & 1) * 64 + h * 32 + lc));
                LDSM_X4T(bf[h], st + P_B + pb + swo);
            }
#pragma unroll
            for (int mt = 0; mt < 2; mt++)
#pragma unroll
                for (int nt = 0; nt < 4; nt++) {
                    int h = nt >> 1, pr = (nt & 1) * 2;
                    MMA16816(acc[mt][nt], ah[mt], bf[h][pr], bf[h][pr + 1]);
                }
        }
        __syncthreads();
        if (chunk + 3 < 8) load_chunk(chunk + 3, (chunk + 3) & 3);
        CP_COMMIT();
    }

    int l4 = l >> 2, l2 = (l & 3) << 1;
#pragma unroll
    for (int mt = 0; mt < 2; mt++)
#pragma unroll
        for (int half = 0; half < 2; half++) {
            int row = bm + wm * 32 + mt * 16 + l4 + half * 8;
            if (OUTHALF) {
                __half* base = (__half*)outp + ((size_t)bz * C_ + row) * 512;
#pragma unroll
                for (int nt = 0; nt < 4; nt++) {
                    int col = bn + wn * 32 + nt * 8 + l2;
                    *(uint32_t*)(base + col) =
                        pack2h(__float2half_rn(acc[mt][nt][half * 2]),
                               __float2half_rn(acc[mt][nt][half * 2 + 1]));
                }
            } else {
                float* base = (float*)outp + ((size_t)bz * C_ + row) * NPIX;
#pragma unroll
                for (int nt = 0; nt < 4; nt++) {
                    int col = bn + wn * 32 + nt * 8 + l2;
                    *(float2*)(base + col) =
                        make_float2(acc[mt][nt][half * 2], acc[mt][nt][half * 2 + 1]);
                }
            }
        }
}

// ---------------- launch ----------------
extern "C" void kernel_launch(void* const* d_in, const int* in_sizes, int n_in,
                              void* d_out, int out_size) {
    const float* x  = (const float*)d_in[0];
    const float* dw = (const float*)d_in[1];
    const float* qw = (const float*)d_in[2];
    const float* kw = (const float*)d_in[3];
    const float* vw = (const float*)d_in[4];
    const float* pw = (const float*)d_in[5];
    float* out = (float*)d_out;

    __half *yp, *whp, *wpp, *wppp;
    cudaGetSymbolAddress((void**)&yp,   g_y);
    cudaGetSymbolAddress((void**)&whp,  g_wh);
    cudaGetSymbolAddress((void**)&wpp,  g_wp);
    cudaGetSymbolAddress((void**)&wppp, g_wpp);

    cudaFuncSetAttribute((const void*)gram_kernel,  cudaFuncAttributeMaxDynamicSharedMemorySize, GR_SMEM);
    cudaFuncSetAttribute((const void*)gemmT_kernel, cudaFuncAttributeMaxDynamicSharedMemorySize, T_SMEM);
    cudaFuncSetAttribute((const void*)scores_kernel, cudaFuncAttributeMaxDynamicSharedMemorySize, S2_SMEM);
    cudaFuncSetAttribute((const void*)wprime_kernel, cudaFuncAttributeMaxDynamicSharedMemorySize, WP_SMEM);
    cudaFuncSetAttribute((const void*)gemm_ab_kernel<0>, cudaFuncAttributeMaxDynamicSharedMemorySize, P_SMEM);
    cudaFuncSetAttribute((const void*)gemm_ab_kernel<1>, cudaFuncAttributeMaxDynamicSharedMemorySize, P_SMEM);

    // 1: dwconv + weight convert + zero g_sq
    prep_kernel<<<4096 + 4096, 256>>>(x, dw, qw, kw, vw, pw);
    // 2: G = Y Y^T (split-K 2, fp32 partials)
    gram_kernel<<<dim3(4, 4, 16), 256, GR_SMEM>>>();
    // 3: reduce partials -> G hi/lo fp16
    gcvt_kernel<<<2048, 256>>>();
    // 4: T = [Wq;Wk;Wv] G (2-term) + rq/rk/rv row dots
    gemmT_kernel<<<dim3(4, 12, 8), 256, T_SMEM>>>();
    // 5: scores + softmax per (b,h)
    scores_kernel<<<B_ * HEADS_, 256, S2_SMEM>>>();
    // 6: W' = P blockdiag(A)
    wprime_kernel<<<dim3(2, B_ * HEADS_), 256, WP_SMEM>>>();
    // 7: W'' = W' Wv   (B = Wv rows, row stride 512, shared across batch)
    gemm_ab_kernel<1><<<dim3(4, 8, 8), 256, P_SMEM>>>(wpp, whp + 2 * C_ * C_, wppp, 512, 0);
    // 8: out = W'' y   (B = y, row stride NPIX, per-batch)
    gemm_ab_kernel<0><<<dim3(NPIX / 128, 8, 8), 256, P_SMEM>>>(wppp, yp, out, NPIX, (size_t)C_ * NPIX);
}